// round 8
// baseline (speedup 1.0000x reference)
#include <cuda_runtime.h>
#include <cuda_bf16.h>
#include <math.h>

#define Nn 2048
#define Dd 512
#define M_LZ 128
#define NB 32               // persistent blocks (fewer arrivals -> cheap grid barrier)
#define NT 256
#define NWARP ((NB * NT) / 32)   // 256 global warps
#define STRIPES 4
#ifndef SIGN_CONV
#define SIGN_CONV (-1.0)
#endif

// ---------------- device scratch (static; no runtime allocation) -------------
__device__ float g_q[Nn];
__device__ float g_deg[Nn];
__device__ float g_V[(M_LZ + 1) * Nn];  // row 0 = ones/sqrt(N); rows 1..M Lanczos basis
__device__ float g_w[Nn];               // raw (unnormalized) candidate vector w_j
__device__ float g_ub[Nn];              // ubar = L * w_raw (unscaled)
__device__ float g_u[Nn];               // u after scaling / pass-1 subtraction
__device__ float g_c1[M_LZ + 2];
__device__ float g_c2[M_LZ + 2];
__device__ float g_alpha[M_LZ + 2];     // T diagonal (1-based)
__device__ float g_beta2[M_LZ + 2];     // ||w entering iter j||^2 (1-based)
__device__ float g_mean;
__device__ double g_yd[M_LZ];           // tridiagonal eigenvector
__device__ float g_fv[Nn];              // assembled Fiedler vector (unnormalized)
__device__ float g_z[Nn];               // z = L * fv
// grid barrier state (generation counter survives graph replays)
__device__ unsigned g_cnt;
__device__ volatile unsigned g_gen;

// ---------------- reduction helpers ------------------------------------------
__device__ __forceinline__ float warpReduceSumF(float v) {
#pragma unroll
    for (int o = 16; o; o >>= 1) v += __shfl_down_sync(0xffffffffu, v, o);
    return v;
}
__device__ __forceinline__ double warpReduceSumD(double v) {
#pragma unroll
    for (int o = 16; o; o >>= 1) v += __shfl_down_sync(0xffffffffu, v, o);
    return v;
}
__device__ __forceinline__ float blockReduceSumF(float v, float* sh) {
    int lane = threadIdx.x & 31, wid = threadIdx.x >> 5;
    v = warpReduceSumF(v);
    __syncthreads();
    if (lane == 0) sh[wid] = v;
    __syncthreads();
    if (wid == 0) {
        int nw = (blockDim.x + 31) >> 5;
        float s = (lane < nw) ? sh[lane] : 0.f;
        s = warpReduceSumF(s);
        if (lane == 0) sh[0] = s;
    }
    __syncthreads();
    return sh[0];
}
__device__ __forceinline__ double blockReduceSumD(double v, double* sh) {
    int lane = threadIdx.x & 31, wid = threadIdx.x >> 5;
    v = warpReduceSumD(v);
    __syncthreads();
    if (lane == 0) sh[wid] = v;
    __syncthreads();
    if (wid == 0) {
        int nw = (blockDim.x + 31) >> 5;
        double s = (lane < nw) ? sh[lane] : 0.0;
        s = warpReduceSumD(s);
        if (lane == 0) sh[0] = s;
    }
    __syncthreads();
    return sh[0];
}

__device__ __forceinline__ float sigmoidf_(float s) {
    if (s >= 0.f) { float ez = __expf(-s); return 1.f / (1.f + ez); }
    float ez = __expf(s); return ez / (1.f + ez);
}

// grid-wide barrier (NB arrivals)
__device__ __forceinline__ void gbar() {
    __syncthreads();
    if (threadIdx.x == 0) {
        __threadfence();
        unsigned gen = g_gen;
        if (atomicAdd(&g_cnt, 1u) == NB - 1u) {
            g_cnt = 0;
            __threadfence();
            g_gen = gen + 1;
        } else {
            while (g_gen == gen) { __nanosleep(20); }
        }
        __threadfence();
    }
    __syncthreads();
}

// ---------------- q_i = sum_k w_k x_ik^2 -------------------------------------
__global__ void k_q(const float* __restrict__ x, const float* __restrict__ w) {
    __shared__ float sh[4];
    int i = blockIdx.x, tid = threadIdx.x;
    float acc = 0.f;
    for (int k = tid; k < Dd; k += 128) {
        float xv = x[(size_t)i * Dd + k];
        acc = fmaf(w[k] * xv, xv, acc);
    }
    acc = blockReduceSumF(acc, sh);
    if (tid == 0) g_q[i] = acc;
}

// ---------------- G = sigmoid(q_i + q_j - 2*X diag(w) X^T + b) ---------------
__global__ void k_gemm(const float* __restrict__ x, const float* __restrict__ w,
                       const float* __restrict__ bptr, float* __restrict__ G) {
    __shared__ float As[16][132];
    __shared__ float Bs[16][132];
    int bm = blockIdx.y * 128, bn = blockIdx.x * 128;
    int tid = threadIdx.x;
    int tx = tid & 15, ty = tid >> 4;
    float acc[8][8];
#pragma unroll
    for (int i = 0; i < 8; i++)
#pragma unroll
        for (int j = 0; j < 8; j++) acc[i][j] = 0.f;

    for (int k0 = 0; k0 < Dd; k0 += 16) {
#pragma unroll
        for (int s = 0; s < 8; s++) {
            int li = tid + s * 256;
            int r = li >> 4, kk = li & 15;
            As[kk][r] = x[(size_t)(bm + r) * Dd + k0 + kk] * w[k0 + kk];
            Bs[kk][r] = x[(size_t)(bn + r) * Dd + k0 + kk];
        }
        __syncthreads();
#pragma unroll
        for (int kk = 0; kk < 16; kk++) {
            float a[8], bb[8];
#pragma unroll
            for (int i = 0; i < 8; i++) a[i] = As[kk][ty * 8 + i];
#pragma unroll
            for (int j = 0; j < 8; j++) bb[j] = Bs[kk][tx * 8 + j];
#pragma unroll
            for (int i = 0; i < 8; i++)
#pragma unroll
                for (int j = 0; j < 8; j++) acc[i][j] = fmaf(a[i], bb[j], acc[i][j]);
        }
        __syncthreads();
    }
    float bv = bptr[0];
#pragma unroll
    for (int i = 0; i < 8; i++) {
        int row = bm + ty * 8 + i;
        float qi = g_q[row] + bv;
#pragma unroll
        for (int j = 0; j < 8; j += 4) {
            int col = bn + tx * 8 + j;
            float4 o;
            o.x = sigmoidf_(qi + g_q[col + 0] - 2.f * acc[i][j + 0]);
            o.y = sigmoidf_(qi + g_q[col + 1] - 2.f * acc[i][j + 1]);
            o.z = sigmoidf_(qi + g_q[col + 2] - 2.f * acc[i][j + 2]);
            o.w = sigmoidf_(qi + g_q[col + 3] - 2.f * acc[i][j + 3]);
            *reinterpret_cast<float4*>(&G[(size_t)row * Nn + col]) = o;
        }
    }
}

// ---------------- degree = row sums of G -------------------------------------
__global__ void k_rowsum(const float* __restrict__ G) {
    __shared__ float sh[8];
    int i = blockIdx.x, tid = threadIdx.x;
    const float* row = G + (size_t)i * Nn;
    float acc = 0.f;
    for (int t = tid; t < Nn; t += 256) acc += row[t];
    acc = blockReduceSumF(acc, sh);
    if (tid == 0) g_deg[i] = acc;
}

// ---------------- persistent Lanczos (entire m-step loop, 1 kernel) ----------
__global__ void __launch_bounds__(NT) k_lanczos(const float* __restrict__ G) {
    const int tid = threadIdx.x;
    const int gid = blockIdx.x * NT + tid;
    const int gw = gid >> 5, lane = gid & 31;

    // ---- init: zero scalars, build v1 = hash - mean, V0 = ones/sqrt(N)
    float r = 0.f;
    if (gid < Nn) {
        unsigned u = (unsigned)(gid + 1) * 2654435761u;
        u ^= u >> 16; u *= 2246822519u; u ^= u >> 13; u *= 3266489917u; u ^= u >> 16;
        r = (float)(u & 0xFFFFFFu) * (1.f / 16777216.f) - 0.5f;
        g_V[gid] = rsqrtf((float)Nn);
    }
    if (gid < M_LZ + 2) g_beta2[gid] = 0.f;
    if (gid == 0) g_mean = 0.f;
    gbar();
    if (gw < Nn / 32) {
        float s = warpReduceSumF(r);
        if (lane == 0) atomicAdd(&g_mean, s);
    }
    gbar();
    if (gid < Nn) g_w[gid] = r - g_mean * (1.f / (float)Nn);
    gbar();

    for (int j = 1; j <= M_LZ; j++) {
        // ---- Phase A: ubar = deg.*w - G*w (raw w); beta2[j] = ||w||^2
        if (gid < Nn) {
            float wv = g_w[gid];
            float p = warpReduceSumF(wv * wv);
            if (lane == 0) atomicAdd(&g_beta2[j], p);
        }
        {
            const float4* w4 = reinterpret_cast<const float4*>(g_w);
            for (int row = gw; row < Nn; row += NWARP) {
                const float4* Gr = reinterpret_cast<const float4*>(G + (size_t)row * Nn);
                float acc = 0.f;
#pragma unroll 4
                for (int t = lane; t < Nn / 4; t += 32) {
                    float4 gv = Gr[t], wv = w4[t];
                    acc += gv.x * wv.x + gv.y * wv.y + gv.z * wv.z + gv.w * wv.w;
                }
                acc = warpReduceSumF(acc);
                if (lane == 0) g_ub[row] = g_deg[row] * g_w[row] - acc;
            }
        }
        gbar();

        // ---- Phase B: commit V[j] = w*invb; u = ubar*invb; dots1 (scaled)
        float invb = rsqrtf(fmaxf(g_beta2[j], 1e-30f));
        if (gid < Nn) {
            float wv = g_w[gid];
            g_V[(size_t)j * Nn + gid] = wv * invb;
            g_u[gid] = g_ub[gid] * invb;
        }
        if (gw <= j) {
            const float4* ub4 = reinterpret_cast<const float4*>(g_ub);
            float acc = 0.f;
            if (gw == j) {
                const float4* w4 = reinterpret_cast<const float4*>(g_w);
#pragma unroll 4
                for (int t = lane; t < Nn / 4; t += 32) {
                    float4 a = w4[t], bq = ub4[t];
                    acc += a.x * bq.x + a.y * bq.y + a.z * bq.z + a.w * bq.w;
                }
                acc = warpReduceSumF(acc) * (invb * invb);
            } else {
                const float4* vi = reinterpret_cast<const float4*>(g_V + (size_t)gw * Nn);
#pragma unroll 4
                for (int t = lane; t < Nn / 4; t += 32) {
                    float4 a = vi[t], bq = ub4[t];
                    acc += a.x * bq.x + a.y * bq.y + a.z * bq.z + a.w * bq.w;
                }
                acc = warpReduceSumF(acc) * invb;
            }
            if (lane == 0) g_c1[gw] = acc;
        }
        gbar();

        // ---- Phase C: u -= sum_i c1_i V_i (STRIPES stripes, atomics)
        {
            int s = gid >> 11, t = gid & (Nn - 1);
            float part = 0.f;
#pragma unroll 4
            for (int i = s; i <= j; i += STRIPES)
                part = fmaf(g_c1[i], g_V[(size_t)i * Nn + t], part);
            if (part != 0.f) atomicAdd(&g_u[t], -part);
        }
        gbar();

        // ---- Phase D: dots2; pre-seed w = u
        if (gid < Nn) g_w[gid] = g_u[gid];
        if (gw <= j) {
            const float4* u4 = reinterpret_cast<const float4*>(g_u);
            const float4* vi = reinterpret_cast<const float4*>(g_V + (size_t)gw * Nn);
            float acc = 0.f;
#pragma unroll 4
            for (int t = lane; t < Nn / 4; t += 32) {
                float4 a = vi[t], bq = u4[t];
                acc += a.x * bq.x + a.y * bq.y + a.z * bq.z + a.w * bq.w;
            }
            acc = warpReduceSumF(acc);
            if (lane == 0) g_c2[gw] = acc;
        }
        gbar();

        // ---- Phase E: w -= sum_i c2_i V_i; alpha_j = c1_j + c2_j
        {
            int s = gid >> 11, t = gid & (Nn - 1);
            float part = 0.f;
#pragma unroll 4
            for (int i = s; i <= j; i += STRIPES)
                part = fmaf(g_c2[i], g_V[(size_t)i * Nn + t], part);
            if (part != 0.f) atomicAdd(&g_w[t], -part);
            if (gid == 0) g_alpha[j] = g_c1[j] + g_c2[j];
        }
        gbar();
    }
}

// ---------------- smallest eigenpair of T (m tridiagonal), one warp ----------
__global__ void k_tridiag() {
    __shared__ double aa[M_LZ], bb2[M_LZ], bb[M_LZ];
    __shared__ double dw[M_LZ], ew[M_LZ], fw[M_LZ], yv[M_LZ], rv[M_LZ];
    __shared__ double sx[32];
    __shared__ int scnt[32];
    __shared__ double slo, shi;
    int lane = threadIdx.x;
    for (int i = lane; i < M_LZ; i += 32) {
        aa[i] = (double)g_alpha[i + 1];
        double b2 = (i < M_LZ - 1) ? (double)g_beta2[i + 2] : 0.0;
        bb2[i] = b2;
        bb[i] = sqrt(b2);
    }
    __syncwarp();
    if (lane == 0) {
        double lo = 1e300, hi = -1e300;
        for (int i = 0; i < M_LZ; i++) {
            double bl = (i > 0) ? bb[i - 1] : 0.0;
            double br = (i < M_LZ - 1) ? bb[i] : 0.0;
            lo = fmin(lo, aa[i] - bl - br);
            hi = fmax(hi, aa[i] + bl + br);
        }
        slo = lo - 1.0; shi = hi + 1.0;
    }
    __syncwarp();
    for (int round = 0; round < 8; round++) {
        double lo = slo, hi = shi;
        double x = lo + (hi - lo) * (double)(lane + 1) * (1.0 / 33.0);
        double d = aa[0] - x;
        int cnt = (d < 0.0);
        for (int i = 1; i < M_LZ; i++) {
            if (fabs(d) < 1e-280) d = (d < 0.0 ? -1e-280 : 1e-280);
            d = aa[i] - x - bb2[i - 1] / d;
            cnt += (d < 0.0);
        }
        sx[lane] = x; scnt[lane] = cnt;
        __syncwarp();
        if (lane == 0) {
            double nlo = lo, nhi = hi;
            int k = 0;
            while (k < 32 && scnt[k] < 1) k++;
            if (k < 32) { nhi = sx[k]; if (k > 0) nlo = sx[k - 1]; }
            else        { nlo = sx[31]; }
            slo = nlo; shi = nhi;
        }
        __syncwarp();
    }
    double th = 0.5 * (slo + shi);
    if (lane == 0) {
        for (int i = 0; i < M_LZ; i++) rv[i] = 1.0;
        for (int it = 0; it < 3; it++) {
            for (int i = 0; i < M_LZ; i++) {
                dw[i] = aa[i] - th;
                ew[i] = (i < M_LZ - 1) ? bb[i] : 0.0;
                fw[i] = 0.0;
                yv[i] = rv[i];
            }
            for (int i = 0; i < M_LZ - 1; i++) {
                double s = bb[i];
                if (fabs(s) > fabs(dw[i])) {
                    double od = dw[i], oe = ew[i], of = fw[i];
                    dw[i] = s;       ew[i] = dw[i + 1]; fw[i] = ew[i + 1];
                    s = od;          dw[i + 1] = oe;    ew[i + 1] = of;
                    double ry = yv[i]; yv[i] = yv[i + 1]; yv[i + 1] = ry;
                }
                double p = dw[i];
                if (fabs(p) < 1e-280) { p = (p < 0.0 ? -1e-280 : 1e-280); dw[i] = p; }
                double m = s / p;
                dw[i + 1] -= m * ew[i];
                ew[i + 1] -= m * fw[i];
                yv[i + 1] -= m * yv[i];
            }
            for (int i = M_LZ - 1; i >= 0; i--) {
                double v = yv[i];
                if (i + 1 < M_LZ) v -= ew[i] * yv[i + 1];
                if (i + 2 < M_LZ) v -= fw[i] * yv[i + 2];
                double p = dw[i];
                if (fabs(p) < 1e-280) p = (p < 0.0 ? -1e-280 : 1e-280);
                yv[i] = v / p;
            }
            double n2 = 0.0;
            for (int i = 0; i < M_LZ; i++) n2 += yv[i] * yv[i];
            double inv = 1.0 / sqrt(n2);
            for (int i = 0; i < M_LZ; i++) rv[i] = yv[i] * inv;
        }
        for (int i = 0; i < M_LZ; i++) g_yd[i] = rv[i];
    }
}

// ---------------- fv = sum_r y_{r-1} V[r] -------------------------------------
__global__ void k_assemble() {
    int t = blockIdx.x * 256 + threadIdx.x;
    float acc = 0.f;
    for (int rr = 1; rr <= M_LZ; rr++)
        acc = fmaf((float)g_yd[rr - 1], g_V[(size_t)rr * Nn + t], acc);
    g_fv[t] = acc;
}

// ---------------- z = L * fv (fp32) -------------------------------------------
__global__ void k_rq(const float* __restrict__ G) {
    __shared__ float sh[8];
    int i = blockIdx.x, tid = threadIdx.x;
    const float* row = G + (size_t)i * Nn;
    float acc = 0.f;
    for (int t = tid; t < Nn; t += 256) acc = fmaf(row[t], g_fv[t], acc);
    acc = blockReduceSumF(acc, sh);
    if (tid == 0) g_z[i] = g_deg[i] * g_fv[i] - acc;
}

// ---------------- value = fv.z / fv.fv; normalize + sign + write --------------
__global__ void k_final(float* __restrict__ out) {
    __shared__ double sh[32];
    __shared__ float sabs[32];
    __shared__ int sidx[32];
    __shared__ double ssign;
    int tid = threadIdx.x;
    double a = (double)g_fv[tid], b = (double)g_fv[tid + 1024];
    double num = blockReduceSumD(a * (double)g_z[tid] + b * (double)g_z[tid + 1024], sh);
    double den = blockReduceSumD(a * a + b * b, sh);
    float bav; int bix;
    float fa = (float)fabs(a), fb = (float)fabs(b);
    if (fa >= fb) { bav = fa; bix = tid; }
    else          { bav = fb; bix = tid + 1024; }
#pragma unroll
    for (int o = 16; o; o >>= 1) {
        float ov = __shfl_down_sync(0xffffffffu, bav, o);
        int   oi = __shfl_down_sync(0xffffffffu, bix, o);
        if (ov > bav || (ov == bav && oi < bix)) { bav = ov; bix = oi; }
    }
    int lane = tid & 31, wid = tid >> 5;
    if (lane == 0) { sabs[wid] = bav; sidx[wid] = bix; }
    __syncthreads();
    if (tid == 0) {
        float bv = sabs[0]; int bi = sidx[0];
        for (int i = 1; i < 32; i++)
            if (sabs[i] > bv || (sabs[i] == bv && sidx[i] < bi)) { bv = sabs[i]; bi = sidx[i]; }
        ssign = (g_fv[bi] >= 0.f ? 1.0 : -1.0) * SIGN_CONV;
        out[(size_t)Nn * Nn] = (float)(num / fmax(den, 1e-300));
    }
    __syncthreads();
    double sc = ssign / sqrt(fmax(den, 1e-300));
    size_t base = (size_t)Nn * Nn + 1;
    out[base + tid]        = (float)(a * sc);
    out[base + tid + 1024] = (float)(b * sc);
}

// ---------------- launcher ----------------------------------------------------
extern "C" void kernel_launch(void* const* d_in, const int* in_sizes, int n_in,
                              void* d_out, int out_size) {
    const float* x = (const float*)d_in[0];
    const float* w = (const float*)d_in[1];
    const float* b = (const float*)d_in[2];
    float* out = (float*)d_out;
    float* G = out;   // grouping matrix lives at the front of d_out

    k_q<<<Nn, 128>>>(x, w);
    k_gemm<<<dim3(Nn / 128, Nn / 128), 256>>>(x, w, b, G);
    k_rowsum<<<Nn, 256>>>(G);
    k_lanczos<<<NB, NT>>>(G);
    k_tridiag<<<1, 32>>>();
    k_assemble<<<Nn / 256, 256>>>();
    k_rq<<<Nn, 256>>>(G);
    k_final<<<1, 1024>>>(out);
}

// round 9
// speedup vs baseline: 1.3212x; 1.3212x over previous
#include <cuda_runtime.h>
#include <cuda_bf16.h>
#include <math.h>

#define Nn 2048
#define Dd 512
#define M_LZ 128
#define NB 148              // persistent blocks (1 CTA/SM)
#define NT 256
#define NWARP ((NB * NT) / 32)   // 1184 global warps
#ifndef SIGN_CONV
#define SIGN_CONV (-1.0)
#endif

// ---------------- device scratch (static; no runtime allocation) -------------
__device__ float g_q[Nn];
__device__ float g_deg[Nn];
__device__ float g_V[(M_LZ + 1) * Nn];   // row 0 = ones/sqrt(N); rows 1..M basis
__device__ float g_LV[(M_LZ + 1) * Nn];  // rows 1..M: L * v_i (normalized)
__device__ float g_w[Nn];                // raw candidate vector w_j
__device__ float g_ub[Nn];               // ubar = L * w_raw
__device__ float g_u[Nn];                // u after sub1
__device__ float g_c1[M_LZ + 2];         // pass-1 raw dots (vs w_raw), i=1..j-1
__device__ float g_c2[M_LZ + 2];         // pass-2 dots
__device__ float g_alpha[M_LZ + 2];      // T diagonal (1-based)
__device__ float g_beta2[M_LZ + 2];      // ||w entering iter j||^2 (totals)
__device__ float g_b2part[64];           // per-owner-warp partials of ||w||^2
__device__ float g_swu;                  // w . ubar accumulator
__device__ float g_ssum;                 // sum(ubar) accumulator
__device__ float g_mean;
__device__ double g_yd[M_LZ];
__device__ float g_fv[Nn];
__device__ float g_z[Nn];
// grid barrier state
__device__ unsigned g_cnt8[8 * 32];      // 8 group counters, 128B apart
__device__ unsigned g_root;
__device__ volatile unsigned g_gen;

// ---------------- reduction helpers ------------------------------------------
__device__ __forceinline__ float warpReduceSumF(float v) {
#pragma unroll
    for (int o = 16; o; o >>= 1) v += __shfl_down_sync(0xffffffffu, v, o);
    return v;
}
__device__ __forceinline__ double warpReduceSumD(double v) {
#pragma unroll
    for (int o = 16; o; o >>= 1) v += __shfl_down_sync(0xffffffffu, v, o);
    return v;
}
__device__ __forceinline__ float blockReduceSumF(float v, float* sh) {
    int lane = threadIdx.x & 31, wid = threadIdx.x >> 5;
    v = warpReduceSumF(v);
    __syncthreads();
    if (lane == 0) sh[wid] = v;
    __syncthreads();
    if (wid == 0) {
        int nw = (blockDim.x + 31) >> 5;
        float s = (lane < nw) ? sh[lane] : 0.f;
        s = warpReduceSumF(s);
        if (lane == 0) sh[0] = s;
    }
    __syncthreads();
    return sh[0];
}
__device__ __forceinline__ double blockReduceSumD(double v, double* sh) {
    int lane = threadIdx.x & 31, wid = threadIdx.x >> 5;
    v = warpReduceSumD(v);
    __syncthreads();
    if (lane == 0) sh[wid] = v;
    __syncthreads();
    if (wid == 0) {
        int nw = (blockDim.x + 31) >> 5;
        double s = (lane < nw) ? sh[lane] : 0.0;
        s = warpReduceSumD(s);
        if (lane == 0) sh[0] = s;
    }
    __syncthreads();
    return sh[0];
}

__device__ __forceinline__ float sigmoidf_(float s) {
    if (s >= 0.f) { float ez = __expf(-s); return 1.f / (1.f + ez); }
    float ez = __expf(s); return ez / (1.f + ez);
}

// ---------------- acq_rel grid barrier (two-level tree, no membar.gl) ---------
__device__ __forceinline__ unsigned atom_add_acqrel(unsigned* p, unsigned v) {
    unsigned old;
    asm volatile("atom.acq_rel.gpu.global.add.u32 %0, [%1], %2;"
                 : "=r"(old) : "l"(p), "r"(v) : "memory");
    return old;
}
__device__ __forceinline__ void st_release_u32(volatile unsigned* p, unsigned v) {
    asm volatile("st.release.gpu.global.u32 [%0], %1;" :: "l"(p), "r"(v) : "memory");
}
__device__ __forceinline__ unsigned ld_acquire_u32(volatile unsigned* p) {
    unsigned v;
    asm volatile("ld.acquire.gpu.global.u32 %0, [%1];" : "=r"(v) : "l"(p) : "memory");
    return v;
}
__device__ __forceinline__ void gbar() {
    __syncthreads();
    if (threadIdx.x == 0) {
        unsigned gen = *(volatile unsigned*)&g_gen;  // exact: release impossible before own arrival
        int grp = blockIdx.x & 7;
        unsigned gsz = (unsigned)(NB >> 3) + ((unsigned)grp < (unsigned)(NB & 7) ? 1u : 0u);
        bool rel = false;
        if (atom_add_acqrel(&g_cnt8[grp * 32], 1u) == gsz - 1u) {
            g_cnt8[grp * 32] = 0;
            if (atom_add_acqrel(&g_root, 1u) == 7u) {
                g_root = 0;
                st_release_u32(&g_gen, gen + 1);
                rel = true;
            }
        }
        if (!rel) {
            while (ld_acquire_u32(&g_gen) == gen) __nanosleep(16);
        }
    }
    __syncthreads();
}

// ---------------- q_i = sum_k w_k x_ik^2 -------------------------------------
__global__ void k_q(const float* __restrict__ x, const float* __restrict__ w) {
    __shared__ float sh[4];
    int i = blockIdx.x, tid = threadIdx.x;
    float acc = 0.f;
    for (int k = tid; k < Dd; k += 128) {
        float xv = x[(size_t)i * Dd + k];
        acc = fmaf(w[k] * xv, xv, acc);
    }
    acc = blockReduceSumF(acc, sh);
    if (tid == 0) g_q[i] = acc;
}

// ---------------- G = sigmoid(q_i + q_j - 2*X diag(w) X^T + b) ---------------
__global__ void k_gemm(const float* __restrict__ x, const float* __restrict__ w,
                       const float* __restrict__ bptr, float* __restrict__ G) {
    __shared__ float As[16][132];
    __shared__ float Bs[16][132];
    int bm = blockIdx.y * 128, bn = blockIdx.x * 128;
    int tid = threadIdx.x;
    int tx = tid & 15, ty = tid >> 4;
    float acc[8][8];
#pragma unroll
    for (int i = 0; i < 8; i++)
#pragma unroll
        for (int j = 0; j < 8; j++) acc[i][j] = 0.f;

    for (int k0 = 0; k0 < Dd; k0 += 16) {
#pragma unroll
        for (int s = 0; s < 8; s++) {
            int li = tid + s * 256;
            int r = li >> 4, kk = li & 15;
            As[kk][r] = x[(size_t)(bm + r) * Dd + k0 + kk] * w[k0 + kk];
            Bs[kk][r] = x[(size_t)(bn + r) * Dd + k0 + kk];
        }
        __syncthreads();
#pragma unroll
        for (int kk = 0; kk < 16; kk++) {
            float a[8], bb[8];
#pragma unroll
            for (int i = 0; i < 8; i++) a[i] = As[kk][ty * 8 + i];
#pragma unroll
            for (int j = 0; j < 8; j++) bb[j] = Bs[kk][tx * 8 + j];
#pragma unroll
            for (int i = 0; i < 8; i++)
#pragma unroll
                for (int j = 0; j < 8; j++) acc[i][j] = fmaf(a[i], bb[j], acc[i][j]);
        }
        __syncthreads();
    }
    float bv = bptr[0];
#pragma unroll
    for (int i = 0; i < 8; i++) {
        int row = bm + ty * 8 + i;
        float qi = g_q[row] + bv;
#pragma unroll
        for (int j = 0; j < 8; j += 4) {
            int col = bn + tx * 8 + j;
            float4 o;
            o.x = sigmoidf_(qi + g_q[col + 0] - 2.f * acc[i][j + 0]);
            o.y = sigmoidf_(qi + g_q[col + 1] - 2.f * acc[i][j + 1]);
            o.z = sigmoidf_(qi + g_q[col + 2] - 2.f * acc[i][j + 2]);
            o.w = sigmoidf_(qi + g_q[col + 3] - 2.f * acc[i][j + 3]);
            *reinterpret_cast<float4*>(&G[(size_t)row * Nn + col]) = o;
        }
    }
}

// ---------------- degree = row sums of G -------------------------------------
__global__ void k_rowsum(const float* __restrict__ G) {
    __shared__ float sh[8];
    int i = blockIdx.x, tid = threadIdx.x;
    const float* row = G + (size_t)i * Nn;
    float acc = 0.f;
    for (int t = tid; t < Nn; t += 256) acc += row[t];
    acc = blockReduceSumF(acc, sh);
    if (tid == 0) g_deg[i] = acc;
}

// ---------------- persistent Lanczos: 4 barriers/iter, symmetric-dot overlap --
__global__ void __launch_bounds__(NT) k_lanczos(const float* __restrict__ G) {
    const int tid = threadIdx.x;
    const int bid = blockIdx.x;
    const int gid = bid * NT + tid;
    const int gw = gid >> 5, lane = gid & 31;
    const bool owner = (bid < 64) && (tid < 32);   // warp 0 of blocks 0..63
    const int town = bid * 32 + lane;              // owned element (valid if owner)
    const float c0 = rsqrtf((float)Nn);

    __shared__ float s_wu, s_sum;

    // ---- init: V0 = ones*c0, zero scalars, v1 = hash - mean
    float r = 0.f;
    if (gid < Nn) {
        unsigned u = (unsigned)(gid + 1) * 2654435761u;
        u ^= u >> 16; u *= 2246822519u; u ^= u >> 13; u *= 3266489917u; u ^= u >> 16;
        r = (float)(u & 0xFFFFFFu) * (1.f / 16777216.f) - 0.5f;
        g_V[gid] = c0;
    }
    if (gid < M_LZ + 2) g_beta2[gid] = 0.f;
    if (gid == 0) { g_mean = 0.f; g_swu = 0.f; g_ssum = 0.f; }
    gbar();
    if (gw < Nn / 32) {
        float s = warpReduceSumF(r);
        if (lane == 0) atomicAdd(&g_mean, s);
    }
    gbar();
    if (gid < Nn) g_w[gid] = r - g_mean * (1.f / (float)Nn);
    gbar();
    if (owner) {   // beta2[1] partials
        float wv = g_w[town];
        float p = warpReduceSumF(wv * wv);
        if (lane == 0) g_b2part[bid] = p;
    }
    // (no barrier needed: b2part consumed in Phase B, after Phase A's barrier)

    for (int j = 1; j <= M_LZ; j++) {
        // ---- Phase A: matvec ubar = D.w - G.w  ||  dots1 c1[i] = LV[i].w (i=1..j-1)
        //               + accumulators swu = w.ubar, ssum = sum(ubar)
        if (tid == 0) { s_wu = 0.f; s_sum = 0.f; }
        __syncthreads();
        const int dotW = j - 1;
        if (gw < dotW) {
            int i = gw + 1;
            const float4* lv = reinterpret_cast<const float4*>(g_LV + (size_t)i * Nn);
            const float4* w4 = reinterpret_cast<const float4*>(g_w);
            float acc = 0.f;
#pragma unroll 4
            for (int t = lane; t < Nn / 4; t += 32) {
                float4 a = lv[t], bq = w4[t];
                acc += a.x * bq.x + a.y * bq.y + a.z * bq.z + a.w * bq.w;
            }
            acc = warpReduceSumF(acc);
            if (lane == 0) g_c1[i] = acc;
        } else {
            const float4* w4 = reinterpret_cast<const float4*>(g_w);
            float lwu = 0.f, lsum = 0.f;
            for (int row = gw - dotW; row < Nn; row += NWARP - dotW) {
                const float4* Gr = reinterpret_cast<const float4*>(G + (size_t)row * Nn);
                float acc = 0.f;
#pragma unroll 4
                for (int t = lane; t < Nn / 4; t += 32) {
                    float4 a = Gr[t], bq = w4[t];
                    acc += a.x * bq.x + a.y * bq.y + a.z * bq.z + a.w * bq.w;
                }
                acc = warpReduceSumF(acc);
                if (lane == 0) {
                    float ub = g_deg[row] * g_w[row] - acc;
                    g_ub[row] = ub;
                    lwu = fmaf(g_w[row], ub, lwu);
                    lsum += ub;
                }
            }
            if (lane == 0 && (lwu != 0.f || lsum != 0.f)) {
                atomicAdd(&s_wu, lwu);
                atomicAdd(&s_sum, lsum);
            }
        }
        __syncthreads();
        if (tid == 0 && (s_wu != 0.f || s_sum != 0.f)) {
            atomicAdd(&g_swu, s_wu);
            atomicAdd(&g_ssum, s_sum);
        }
        gbar();

        // ---- Phase B (owner warps): total beta2; commit V[j], LV[j]; sub1 -> u
        if (owner) {
            float b2 = g_b2part[lane] + g_b2part[lane + 32];
            b2 = warpReduceSumF(b2);
            b2 = __shfl_sync(0xffffffffu, b2, 0);
            float invb = rsqrtf(fmaxf(b2, 1e-30f));
            if (bid == 0 && lane == 0) g_beta2[j] = b2;
            float c1j = g_swu * invb * invb;        // c1_j = v_j . u
            float a0 = c0 * c0 * g_ssum * invb;     // c1_0 * V0 element (constant)
            int t = town;
            float wv = g_w[t];
            float vj = wv * invb;
            float uv = g_ub[t] * invb;
            g_V[(size_t)j * Nn + t] = vj;
            g_LV[(size_t)j * Nn + t] = uv;
            float s = fmaf(c1j, vj, a0);
#pragma unroll 4
            for (int i = 1; i < j; i++)
                s = fmaf(g_c1[i] * invb, g_V[(size_t)i * Nn + t], s);
            g_u[t] = uv - s;
        }
        gbar();

        // ---- Phase C: dots2 c2[i] = V[i] . u, i = 0..j
        if (gw <= j) {
            const float4* u4 = reinterpret_cast<const float4*>(g_u);
            const float4* vi = reinterpret_cast<const float4*>(g_V + (size_t)gw * Nn);
            float acc = 0.f;
#pragma unroll 4
            for (int t = lane; t < Nn / 4; t += 32) {
                float4 a = vi[t], bq = u4[t];
                acc += a.x * bq.x + a.y * bq.y + a.z * bq.z + a.w * bq.w;
            }
            acc = warpReduceSumF(acc);
            if (lane == 0) g_c2[gw] = acc;
        }
        gbar();

        // ---- Phase D (owner warps): sub2 -> w; beta2 partials; alpha; reset accum
        if (owner) {
            int t = town;
            float s = 0.f;
#pragma unroll 4
            for (int i = 0; i <= j; i++)
                s = fmaf(g_c2[i], g_V[(size_t)i * Nn + t], s);
            float wv = g_u[t] - s;
            g_w[t] = wv;
            float p = warpReduceSumF(wv * wv);
            if (lane == 0) g_b2part[bid] = p;
        }
        if (gid == 0) {
            float invb = rsqrtf(fmaxf(g_beta2[j], 1e-30f));
            g_alpha[j] = g_swu * invb * invb + g_c2[j];
            g_swu = 0.f;
            g_ssum = 0.f;
        }
        gbar();
    }
}

// ---------------- smallest eigenpair of T (m tridiagonal), one warp ----------
__global__ void k_tridiag() {
    __shared__ double aa[M_LZ], bb2[M_LZ], bb[M_LZ];
    __shared__ double dw[M_LZ], ew[M_LZ], fw[M_LZ], yv[M_LZ], rv[M_LZ];
    __shared__ double sx[32];
    __shared__ int scnt[32];
    __shared__ double slo, shi;
    int lane = threadIdx.x;
    for (int i = lane; i < M_LZ; i += 32) {
        aa[i] = (double)g_alpha[i + 1];
        double b2 = (i < M_LZ - 1) ? (double)g_beta2[i + 2] : 0.0;
        bb2[i] = b2;
        bb[i] = sqrt(b2);
    }
    __syncwarp();
    if (lane == 0) {
        double lo = 1e300, hi = -1e300;
        for (int i = 0; i < M_LZ; i++) {
            double bl = (i > 0) ? bb[i - 1] : 0.0;
            double br = (i < M_LZ - 1) ? bb[i] : 0.0;
            lo = fmin(lo, aa[i] - bl - br);
            hi = fmax(hi, aa[i] + bl + br);
        }
        slo = lo - 1.0; shi = hi + 1.0;
    }
    __syncwarp();
    for (int round = 0; round < 8; round++) {
        double lo = slo, hi = shi;
        double x = lo + (hi - lo) * (double)(lane + 1) * (1.0 / 33.0);
        double d = aa[0] - x;
        int cnt = (d < 0.0);
        for (int i = 1; i < M_LZ; i++) {
            if (fabs(d) < 1e-280) d = (d < 0.0 ? -1e-280 : 1e-280);
            d = aa[i] - x - bb2[i - 1] / d;
            cnt += (d < 0.0);
        }
        sx[lane] = x; scnt[lane] = cnt;
        __syncwarp();
        if (lane == 0) {
            double nlo = lo, nhi = hi;
            int k = 0;
            while (k < 32 && scnt[k] < 1) k++;
            if (k < 32) { nhi = sx[k]; if (k > 0) nlo = sx[k - 1]; }
            else        { nlo = sx[31]; }
            slo = nlo; shi = nhi;
        }
        __syncwarp();
    }
    double th = 0.5 * (slo + shi);
    if (lane == 0) {
        for (int i = 0; i < M_LZ; i++) rv[i] = 1.0;
        for (int it = 0; it < 3; it++) {
            for (int i = 0; i < M_LZ; i++) {
                dw[i] = aa[i] - th;
                ew[i] = (i < M_LZ - 1) ? bb[i] : 0.0;
                fw[i] = 0.0;
                yv[i] = rv[i];
            }
            for (int i = 0; i < M_LZ - 1; i++) {
                double s = bb[i];
                if (fabs(s) > fabs(dw[i])) {
                    double od = dw[i], oe = ew[i], of = fw[i];
                    dw[i] = s;       ew[i] = dw[i + 1]; fw[i] = ew[i + 1];
                    s = od;          dw[i + 1] = oe;    ew[i + 1] = of;
                    double ry = yv[i]; yv[i] = yv[i + 1]; yv[i + 1] = ry;
                }
                double p = dw[i];
                if (fabs(p) < 1e-280) { p = (p < 0.0 ? -1e-280 : 1e-280); dw[i] = p; }
                double m = s / p;
                dw[i + 1] -= m * ew[i];
                ew[i + 1] -= m * fw[i];
                yv[i + 1] -= m * yv[i];
            }
            for (int i = M_LZ - 1; i >= 0; i--) {
                double v = yv[i];
                if (i + 1 < M_LZ) v -= ew[i] * yv[i + 1];
                if (i + 2 < M_LZ) v -= fw[i] * yv[i + 2];
                double p = dw[i];
                if (fabs(p) < 1e-280) p = (p < 0.0 ? -1e-280 : 1e-280);
                yv[i] = v / p;
            }
            double n2 = 0.0;
            for (int i = 0; i < M_LZ; i++) n2 += yv[i] * yv[i];
            double inv = 1.0 / sqrt(n2);
            for (int i = 0; i < M_LZ; i++) rv[i] = yv[i] * inv;
        }
        for (int i = 0; i < M_LZ; i++) g_yd[i] = rv[i];
    }
}

// ---------------- fv = sum_r y_{r-1} V[r] -------------------------------------
__global__ void k_assemble() {
    int t = blockIdx.x * 256 + threadIdx.x;
    float acc = 0.f;
    for (int rr = 1; rr <= M_LZ; rr++)
        acc = fmaf((float)g_yd[rr - 1], g_V[(size_t)rr * Nn + t], acc);
    g_fv[t] = acc;
}

// ---------------- z = L * fv (fp32) -------------------------------------------
__global__ void k_rq(const float* __restrict__ G) {
    __shared__ float sh[8];
    int i = blockIdx.x, tid = threadIdx.x;
    const float* row = G + (size_t)i * Nn;
    float acc = 0.f;
    for (int t = tid; t < Nn; t += 256) acc = fmaf(row[t], g_fv[t], acc);
    acc = blockReduceSumF(acc, sh);
    if (tid == 0) g_z[i] = g_deg[i] * g_fv[i] - acc;
}

// ---------------- value = fv.z / fv.fv; normalize + sign + write --------------
__global__ void k_final(float* __restrict__ out) {
    __shared__ double sh[32];
    __shared__ float sabs[32];
    __shared__ int sidx[32];
    __shared__ double ssign;
    int tid = threadIdx.x;
    double a = (double)g_fv[tid], b = (double)g_fv[tid + 1024];
    double num = blockReduceSumD(a * (double)g_z[tid] + b * (double)g_z[tid + 1024], sh);
    double den = blockReduceSumD(a * a + b * b, sh);
    float bav; int bix;
    float fa = (float)fabs(a), fb = (float)fabs(b);
    if (fa >= fb) { bav = fa; bix = tid; }
    else          { bav = fb; bix = tid + 1024; }
#pragma unroll
    for (int o = 16; o; o >>= 1) {
        float ov = __shfl_down_sync(0xffffffffu, bav, o);
        int   oi = __shfl_down_sync(0xffffffffu, bix, o);
        if (ov > bav || (ov == bav && oi < bix)) { bav = ov; bix = oi; }
    }
    int lane = tid & 31, wid = tid >> 5;
    if (lane == 0) { sabs[wid] = bav; sidx[wid] = bix; }
    __syncthreads();
    if (tid == 0) {
        float bv = sabs[0]; int bi = sidx[0];
        for (int i = 1; i < 32; i++)
            if (sabs[i] > bv || (sabs[i] == bv && sidx[i] < bi)) { bv = sabs[i]; bi = sidx[i]; }
        ssign = (g_fv[bi] >= 0.f ? 1.0 : -1.0) * SIGN_CONV;
        out[(size_t)Nn * Nn] = (float)(num / fmax(den, 1e-300));
    }
    __syncthreads();
    double sc = ssign / sqrt(fmax(den, 1e-300));
    size_t base = (size_t)Nn * Nn + 1;
    out[base + tid]        = (float)(a * sc);
    out[base + tid + 1024] = (float)(b * sc);
}

// ---------------- launcher ----------------------------------------------------
extern "C" void kernel_launch(void* const* d_in, const int* in_sizes, int n_in,
                              void* d_out, int out_size) {
    const float* x = (const float*)d_in[0];
    const float* w = (const float*)d_in[1];
    const float* b = (const float*)d_in[2];
    float* out = (float*)d_out;
    float* G = out;   // grouping matrix lives at the front of d_out

    k_q<<<Nn, 128>>>(x, w);
    k_gemm<<<dim3(Nn / 128, Nn / 128), 256>>>(x, w, b, G);
    k_rowsum<<<Nn, 256>>>(G);
    k_lanczos<<<NB, NT>>>(G);
    k_tridiag<<<1, 32>>>();
    k_assemble<<<Nn / 256, 256>>>();
    k_rq<<<Nn, 256>>>(G);
    k_final<<<1, 1024>>>(out);
}

// round 10
// speedup vs baseline: 1.8504x; 1.4006x over previous
#include <cuda_runtime.h>
#include <cuda_bf16.h>
#include <math.h>

#define Nn 2048
#define Dd 512
#define M_LZ 128
#define NB 148              // persistent blocks (1 CTA/SM)
#define NT 256
#define NWARP ((NB * NT) / 32)   // 1184 global warps
#ifndef SIGN_CONV
#define SIGN_CONV (-1.0)
#endif

// ---------------- device scratch (static; no runtime allocation) -------------
__device__ float g_q[Nn];
__device__ float g_deg[Nn];
__device__ float g_V[(M_LZ + 1) * Nn];   // row 0 = ones/sqrt(N); rows 1..M basis
__device__ float g_LV[(M_LZ + 1) * Nn];  // rows 1..M: L * v_i (normalized)
__device__ float g_w[Nn];                // raw candidate vector w_j
__device__ float g_ub[Nn];               // ubar = L * w_raw
__device__ float g_acc[Nn];              // pass-1 reorth correction accumulator
__device__ float g_c1[M_LZ + 2];         // pass-1 raw dots (vs w_raw), i=1..j-1
__device__ float g_c2[M_LZ + 2];         // pass-2 dots
__device__ float g_alpha[M_LZ + 2];      // T diagonal (1-based)
__device__ float g_beta2[M_LZ + 2];      // ||w entering iter j||^2 (totals)
__device__ float g_swu;                  // w . ubar accumulator
__device__ float g_ssum;                 // sum(ubar) accumulator
__device__ float g_mean;
__device__ double g_yd[M_LZ];
__device__ float g_fv[Nn];
__device__ float g_z[Nn];
// grid barrier state
__device__ unsigned g_cnt8[8 * 32];      // 8 group counters, 128B apart
__device__ unsigned g_root;
__device__ volatile unsigned g_gen;

// ---------------- reduction helpers ------------------------------------------
__device__ __forceinline__ float warpReduceSumF(float v) {
#pragma unroll
    for (int o = 16; o; o >>= 1) v += __shfl_down_sync(0xffffffffu, v, o);
    return v;
}
__device__ __forceinline__ double warpReduceSumD(double v) {
#pragma unroll
    for (int o = 16; o; o >>= 1) v += __shfl_down_sync(0xffffffffu, v, o);
    return v;
}
__device__ __forceinline__ float blockReduceSumF(float v, float* sh) {
    int lane = threadIdx.x & 31, wid = threadIdx.x >> 5;
    v = warpReduceSumF(v);
    __syncthreads();
    if (lane == 0) sh[wid] = v;
    __syncthreads();
    if (wid == 0) {
        int nw = (blockDim.x + 31) >> 5;
        float s = (lane < nw) ? sh[lane] : 0.f;
        s = warpReduceSumF(s);
        if (lane == 0) sh[0] = s;
    }
    __syncthreads();
    return sh[0];
}
__device__ __forceinline__ double blockReduceSumD(double v, double* sh) {
    int lane = threadIdx.x & 31, wid = threadIdx.x >> 5;
    v = warpReduceSumD(v);
    __syncthreads();
    if (lane == 0) sh[wid] = v;
    __syncthreads();
    if (wid == 0) {
        int nw = (blockDim.x + 31) >> 5;
        double s = (lane < nw) ? sh[lane] : 0.0;
        s = warpReduceSumD(s);
        if (lane == 0) sh[0] = s;
    }
    __syncthreads();
    return sh[0];
}

__device__ __forceinline__ float sigmoidf_(float s) {
    if (s >= 0.f) { float ez = __expf(-s); return 1.f / (1.f + ez); }
    float ez = __expf(s); return ez / (1.f + ez);
}

// ---------------- acq_rel grid barrier (two-level tree) -----------------------
__device__ __forceinline__ unsigned atom_add_acqrel(unsigned* p, unsigned v) {
    unsigned old;
    asm volatile("atom.acq_rel.gpu.global.add.u32 %0, [%1], %2;"
                 : "=r"(old) : "l"(p), "r"(v) : "memory");
    return old;
}
__device__ __forceinline__ void st_release_u32(volatile unsigned* p, unsigned v) {
    asm volatile("st.release.gpu.global.u32 [%0], %1;" :: "l"(p), "r"(v) : "memory");
}
__device__ __forceinline__ unsigned ld_acquire_u32(volatile unsigned* p) {
    unsigned v;
    asm volatile("ld.acquire.gpu.global.u32 %0, [%1];" : "=r"(v) : "l"(p) : "memory");
    return v;
}
__device__ __forceinline__ void gbar() {
    __syncthreads();
    if (threadIdx.x == 0) {
        unsigned gen = *(volatile unsigned*)&g_gen;
        int grp = blockIdx.x & 7;
        unsigned gsz = (unsigned)(NB >> 3) + ((unsigned)grp < (unsigned)(NB & 7) ? 1u : 0u);
        bool rel = false;
        if (atom_add_acqrel(&g_cnt8[grp * 32], 1u) == gsz - 1u) {
            g_cnt8[grp * 32] = 0;
            if (atom_add_acqrel(&g_root, 1u) == 7u) {
                g_root = 0;
                st_release_u32(&g_gen, gen + 1);
                rel = true;
            }
        }
        if (!rel) {
            while (ld_acquire_u32(&g_gen) == gen) __nanosleep(16);
        }
    }
    __syncthreads();
}

// ---------------- q_i = sum_k w_k x_ik^2 -------------------------------------
__global__ void k_q(const float* __restrict__ x, const float* __restrict__ w) {
    __shared__ float sh[4];
    int i = blockIdx.x, tid = threadIdx.x;
    float acc = 0.f;
    for (int k = tid; k < Dd; k += 128) {
        float xv = x[(size_t)i * Dd + k];
        acc = fmaf(w[k] * xv, xv, acc);
    }
    acc = blockReduceSumF(acc, sh);
    if (tid == 0) g_q[i] = acc;
}

// ---------------- G = sigmoid(q_i + q_j - 2*X diag(w) X^T + b) ---------------
__global__ void k_gemm(const float* __restrict__ x, const float* __restrict__ w,
                       const float* __restrict__ bptr, float* __restrict__ G) {
    __shared__ float As[16][132];
    __shared__ float Bs[16][132];
    int bm = blockIdx.y * 128, bn = blockIdx.x * 128;
    int tid = threadIdx.x;
    int tx = tid & 15, ty = tid >> 4;
    float acc[8][8];
#pragma unroll
    for (int i = 0; i < 8; i++)
#pragma unroll
        for (int j = 0; j < 8; j++) acc[i][j] = 0.f;

    for (int k0 = 0; k0 < Dd; k0 += 16) {
#pragma unroll
        for (int s = 0; s < 8; s++) {
            int li = tid + s * 256;
            int r = li >> 4, kk = li & 15;
            As[kk][r] = x[(size_t)(bm + r) * Dd + k0 + kk] * w[k0 + kk];
            Bs[kk][r] = x[(size_t)(bn + r) * Dd + k0 + kk];
        }
        __syncthreads();
#pragma unroll
        for (int kk = 0; kk < 16; kk++) {
            float a[8], bb[8];
#pragma unroll
            for (int i = 0; i < 8; i++) a[i] = As[kk][ty * 8 + i];
#pragma unroll
            for (int j = 0; j < 8; j++) bb[j] = Bs[kk][tx * 8 + j];
#pragma unroll
            for (int i = 0; i < 8; i++)
#pragma unroll
                for (int j = 0; j < 8; j++) acc[i][j] = fmaf(a[i], bb[j], acc[i][j]);
        }
        __syncthreads();
    }
    float bv = bptr[0];
#pragma unroll
    for (int i = 0; i < 8; i++) {
        int row = bm + ty * 8 + i;
        float qi = g_q[row] + bv;
#pragma unroll
        for (int j = 0; j < 8; j += 4) {
            int col = bn + tx * 8 + j;
            float4 o;
            o.x = sigmoidf_(qi + g_q[col + 0] - 2.f * acc[i][j + 0]);
            o.y = sigmoidf_(qi + g_q[col + 1] - 2.f * acc[i][j + 1]);
            o.z = sigmoidf_(qi + g_q[col + 2] - 2.f * acc[i][j + 2]);
            o.w = sigmoidf_(qi + g_q[col + 3] - 2.f * acc[i][j + 3]);
            *reinterpret_cast<float4*>(&G[(size_t)row * Nn + col]) = o;
        }
    }
}

// ---------------- degree = row sums of G -------------------------------------
__global__ void k_rowsum(const float* __restrict__ G) {
    __shared__ float sh[8];
    int i = blockIdx.x, tid = threadIdx.x;
    const float* row = G + (size_t)i * Nn;
    float acc = 0.f;
    for (int t = tid; t < Nn; t += 256) acc += row[t];
    acc = blockReduceSumF(acc, sh);
    if (tid == 0) g_deg[i] = acc;
}

// ---------------- persistent Lanczos: 4 barriers/iter, all-wide phases --------
__global__ void __launch_bounds__(NT) k_lanczos(const float* __restrict__ G) {
    const int tid = threadIdx.x;
    const int bid = blockIdx.x;
    const int gid = bid * NT + tid;
    const int gw = gid >> 5, lane = gid & 31;
    const int stripe = gid >> 11;          // 0..18 (16 real stripes + extras)
    const int selem = gid & (Nn - 1);      // element for striped phases
    const float c0 = rsqrtf((float)Nn);

    __shared__ float s_wu, s_sum;

    // ---- init: V0 = ones*c0, zero scalars/acc, v1 = hash - mean
    float r = 0.f;
    if (gid < Nn) {
        unsigned u = (unsigned)(gid + 1) * 2654435761u;
        u ^= u >> 16; u *= 2246822519u; u ^= u >> 13; u *= 3266489917u; u ^= u >> 16;
        r = (float)(u & 0xFFFFFFu) * (1.f / 16777216.f) - 0.5f;
        g_V[gid] = c0;
        g_acc[gid] = 0.f;
    }
    if (gid < M_LZ + 2) g_beta2[gid] = 0.f;
    if (gid == 0) { g_mean = 0.f; g_swu = 0.f; g_ssum = 0.f; }
    gbar();
    if (gw < Nn / 32) {
        float s = warpReduceSumF(r);
        if (lane == 0) atomicAdd(&g_mean, s);
    }
    gbar();
    if (gid < Nn) g_w[gid] = r - g_mean * (1.f / (float)Nn);
    gbar();

    for (int j = 1; j <= M_LZ; j++) {
        // ---- Phase A: matvec ubar = D.w - G.w  ||  dots1 c1[i] = LV[i].w
        //      + beta2[j] = ||w||^2 (first 64 warps) + accumulators swu, ssum
        if (tid == 0) { s_wu = 0.f; s_sum = 0.f; }
        __syncthreads();
        if (gid < Nn) {
            float wv = g_w[gid];
            float p = warpReduceSumF(wv * wv);
            if (lane == 0) atomicAdd(&g_beta2[j], p);
        }
        const int dotW = j - 1;
        if (gw < dotW) {
            int i = gw + 1;
            const float4* lv = reinterpret_cast<const float4*>(g_LV + (size_t)i * Nn);
            const float4* w4 = reinterpret_cast<const float4*>(g_w);
            float acc = 0.f;
#pragma unroll 4
            for (int t = lane; t < Nn / 4; t += 32) {
                float4 a = lv[t], bq = w4[t];
                acc += a.x * bq.x + a.y * bq.y + a.z * bq.z + a.w * bq.w;
            }
            acc = warpReduceSumF(acc);
            if (lane == 0) g_c1[i] = acc;
        } else {
            const float4* w4 = reinterpret_cast<const float4*>(g_w);
            float lwu = 0.f, lsum = 0.f;
            for (int row = gw - dotW; row < Nn; row += NWARP - dotW) {
                const float4* Gr = reinterpret_cast<const float4*>(G + (size_t)row * Nn);
                float acc = 0.f;
#pragma unroll 4
                for (int t = lane; t < Nn / 4; t += 32) {
                    float4 a = Gr[t], bq = w4[t];
                    acc += a.x * bq.x + a.y * bq.y + a.z * bq.z + a.w * bq.w;
                }
                acc = warpReduceSumF(acc);
                if (lane == 0) {
                    float ub = g_deg[row] * g_w[row] - acc;
                    g_ub[row] = ub;
                    lwu = fmaf(g_w[row], ub, lwu);
                    lsum += ub;
                }
            }
            if (lane == 0 && (lwu != 0.f || lsum != 0.f)) {
                atomicAdd(&s_wu, lwu);
                atomicAdd(&s_sum, lsum);
            }
        }
        __syncthreads();
        if (tid == 0 && (s_wu != 0.f || s_sum != 0.f)) {
            atomicAdd(&g_swu, s_wu);
            atomicAdd(&g_ssum, s_sum);
        }
        gbar();

        // ---- Phase B: striped sub1 partials into acc; stripe0 commits V[j],LV[j]
        {
            float invb = rsqrtf(fmaxf(g_beta2[j], 1e-30f));
            if (stripe < 16) {
                int t = selem;
                float part = 0.f;
#pragma unroll 4
                for (int i = 1 + stripe; i < j; i += 16)
                    part = fmaf(g_c1[i] * invb, g_V[(size_t)i * Nn + t], part);
                if (stripe == 0) {
                    float wv = g_w[t];
                    float vj = wv * invb;
                    float uv = g_ub[t] * invb;
                    g_V[(size_t)j * Nn + t] = vj;
                    g_LV[(size_t)j * Nn + t] = uv;
                    float c1j = g_swu * invb * invb;
                    float a0 = c0 * c0 * g_ssum * invb;
                    part += fmaf(c1j, vj, a0);
                }
                if (part != 0.f) atomicAdd(&g_acc[t], part);
            }
        }
        gbar();

        // ---- Phase C: dots2 c2[i] = V[i].(LV[j]-acc)  ||  idle warps seed w=u
        if (gw <= j) {
            const float4* lvj = reinterpret_cast<const float4*>(g_LV + (size_t)j * Nn);
            const float4* ac4 = reinterpret_cast<const float4*>(g_acc);
            const float4* vi = reinterpret_cast<const float4*>(g_V + (size_t)gw * Nn);
            float acc = 0.f;
#pragma unroll 4
            for (int t = lane; t < Nn / 4; t += 32) {
                float4 a = vi[t], u0 = lvj[t], a4 = ac4[t];
                acc += a.x * (u0.x - a4.x) + a.y * (u0.y - a4.y)
                     + a.z * (u0.z - a4.z) + a.w * (u0.w - a4.w);
            }
            acc = warpReduceSumF(acc);
            if (lane == 0) g_c2[gw] = acc;
        } else if (gw <= j + 64) {
            int t = (gw - j - 1) * 32 + lane;
            g_w[t] = g_LV[(size_t)j * Nn + t] - g_acc[t];
        }
        gbar();

        // ---- Phase D: striped sub2 into w; stripe16 zeroes acc; alpha; reset
        if (stripe < 16) {
            int t = selem;
            float part = 0.f;
#pragma unroll 4
            for (int i = stripe; i <= j; i += 16)
                part = fmaf(g_c2[i], g_V[(size_t)i * Nn + t], part);
            if (part != 0.f) atomicAdd(&g_w[t], -part);
        } else if (stripe == 16) {
            g_acc[selem] = 0.f;
        }
        if (gid == 0) {
            float invb = rsqrtf(fmaxf(g_beta2[j], 1e-30f));
            g_alpha[j] = g_swu * invb * invb + g_c2[j];
            g_swu = 0.f;
            g_ssum = 0.f;
        }
        gbar();
    }
}

// ---------------- smallest eigenpair of T (m tridiagonal), one warp ----------
__global__ void k_tridiag() {
    __shared__ double aa[M_LZ], bb2[M_LZ], bb[M_LZ];
    __shared__ double dw[M_LZ], ew[M_LZ], fw[M_LZ], yv[M_LZ], rv[M_LZ];
    __shared__ double sx[32];
    __shared__ int scnt[32];
    __shared__ double slo, shi;
    int lane = threadIdx.x;
    for (int i = lane; i < M_LZ; i += 32) {
        aa[i] = (double)g_alpha[i + 1];
        double b2 = (i < M_LZ - 1) ? (double)g_beta2[i + 2] : 0.0;
        bb2[i] = b2;
        bb[i] = sqrt(b2);
    }
    __syncwarp();
    if (lane == 0) {
        double lo = 1e300, hi = -1e300;
        for (int i = 0; i < M_LZ; i++) {
            double bl = (i > 0) ? bb[i - 1] : 0.0;
            double br = (i < M_LZ - 1) ? bb[i] : 0.0;
            lo = fmin(lo, aa[i] - bl - br);
            hi = fmax(hi, aa[i] + bl + br);
        }
        slo = lo - 1.0; shi = hi + 1.0;
    }
    __syncwarp();
    for (int round = 0; round < 8; round++) {
        double lo = slo, hi = shi;
        double x = lo + (hi - lo) * (double)(lane + 1) * (1.0 / 33.0);
        double d = aa[0] - x;
        int cnt = (d < 0.0);
        for (int i = 1; i < M_LZ; i++) {
            if (fabs(d) < 1e-280) d = (d < 0.0 ? -1e-280 : 1e-280);
            d = aa[i] - x - bb2[i - 1] / d;
            cnt += (d < 0.0);
        }
        sx[lane] = x; scnt[lane] = cnt;
        __syncwarp();
        if (lane == 0) {
            double nlo = lo, nhi = hi;
            int k = 0;
            while (k < 32 && scnt[k] < 1) k++;
            if (k < 32) { nhi = sx[k]; if (k > 0) nlo = sx[k - 1]; }
            else        { nlo = sx[31]; }
            slo = nlo; shi = nhi;
        }
        __syncwarp();
    }
    double th = 0.5 * (slo + shi);
    if (lane == 0) {
        for (int i = 0; i < M_LZ; i++) rv[i] = 1.0;
        for (int it = 0; it < 3; it++) {
            for (int i = 0; i < M_LZ; i++) {
                dw[i] = aa[i] - th;
                ew[i] = (i < M_LZ - 1) ? bb[i] : 0.0;
                fw[i] = 0.0;
                yv[i] = rv[i];
            }
            for (int i = 0; i < M_LZ - 1; i++) {
                double s = bb[i];
                if (fabs(s) > fabs(dw[i])) {
                    double od = dw[i], oe = ew[i], of = fw[i];
                    dw[i] = s;       ew[i] = dw[i + 1]; fw[i] = ew[i + 1];
                    s = od;          dw[i + 1] = oe;    ew[i + 1] = of;
                    double ry = yv[i]; yv[i] = yv[i + 1]; yv[i + 1] = ry;
                }
                double p = dw[i];
                if (fabs(p) < 1e-280) { p = (p < 0.0 ? -1e-280 : 1e-280); dw[i] = p; }
                double m = s / p;
                dw[i + 1] -= m * ew[i];
                ew[i + 1] -= m * fw[i];
                yv[i + 1] -= m * yv[i];
            }
            for (int i = M_LZ - 1; i >= 0; i--) {
                double v = yv[i];
                if (i + 1 < M_LZ) v -= ew[i] * yv[i + 1];
                if (i + 2 < M_LZ) v -= fw[i] * yv[i + 2];
                double p = dw[i];
                if (fabs(p) < 1e-280) p = (p < 0.0 ? -1e-280 : 1e-280);
                yv[i] = v / p;
            }
            double n2 = 0.0;
            for (int i = 0; i < M_LZ; i++) n2 += yv[i] * yv[i];
            double inv = 1.0 / sqrt(n2);
            for (int i = 0; i < M_LZ; i++) rv[i] = yv[i] * inv;
        }
        for (int i = 0; i < M_LZ; i++) g_yd[i] = rv[i];
    }
}

// ---------------- fv = sum_r y_{r-1} V[r] -------------------------------------
__global__ void k_assemble() {
    int t = blockIdx.x * 256 + threadIdx.x;
    float acc = 0.f;
    for (int rr = 1; rr <= M_LZ; rr++)
        acc = fmaf((float)g_yd[rr - 1], g_V[(size_t)rr * Nn + t], acc);
    g_fv[t] = acc;
}

// ---------------- z = L * fv (fp32) -------------------------------------------
__global__ void k_rq(const float* __restrict__ G) {
    __shared__ float sh[8];
    int i = blockIdx.x, tid = threadIdx.x;
    const float* row = G + (size_t)i * Nn;
    float acc = 0.f;
    for (int t = tid; t < Nn; t += 256) acc = fmaf(row[t], g_fv[t], acc);
    acc = blockReduceSumF(acc, sh);
    if (tid == 0) g_z[i] = g_deg[i] * g_fv[i] - acc;
}

// ---------------- value = fv.z / fv.fv; normalize + sign + write --------------
__global__ void k_final(float* __restrict__ out) {
    __shared__ double sh[32];
    __shared__ float sabs[32];
    __shared__ int sidx[32];
    __shared__ double ssign;
    int tid = threadIdx.x;
    double a = (double)g_fv[tid], b = (double)g_fv[tid + 1024];
    double num = blockReduceSumD(a * (double)g_z[tid] + b * (double)g_z[tid + 1024], sh);
    double den = blockReduceSumD(a * a + b * b, sh);
    float bav; int bix;
    float fa = (float)fabs(a), fb = (float)fabs(b);
    if (fa >= fb) { bav = fa; bix = tid; }
    else          { bav = fb; bix = tid + 1024; }
#pragma unroll
    for (int o = 16; o; o >>= 1) {
        float ov = __shfl_down_sync(0xffffffffu, bav, o);
        int   oi = __shfl_down_sync(0xffffffffu, bix, o);
        if (ov > bav || (ov == bav && oi < bix)) { bav = ov; bix = oi; }
    }
    int lane = tid & 31, wid = tid >> 5;
    if (lane == 0) { sabs[wid] = bav; sidx[wid] = bix; }
    __syncthreads();
    if (tid == 0) {
        float bv = sabs[0]; int bi = sidx[0];
        for (int i = 1; i < 32; i++)
            if (sabs[i] > bv || (sabs[i] == bv && sidx[i] < bi)) { bv = sabs[i]; bi = sidx[i]; }
        ssign = (g_fv[bi] >= 0.f ? 1.0 : -1.0) * SIGN_CONV;
        out[(size_t)Nn * Nn] = (float)(num / fmax(den, 1e-300));
    }
    __syncthreads();
    double sc = ssign / sqrt(fmax(den, 1e-300));
    size_t base = (size_t)Nn * Nn + 1;
    out[base + tid]        = (float)(a * sc);
    out[base + tid + 1024] = (float)(b * sc);
}

// ---------------- launcher ----------------------------------------------------
extern "C" void kernel_launch(void* const* d_in, const int* in_sizes, int n_in,
                              void* d_out, int out_size) {
    const float* x = (const float*)d_in[0];
    const float* w = (const float*)d_in[1];
    const float* b = (const float*)d_in[2];
    float* out = (float*)d_out;
    float* G = out;   // grouping matrix lives at the front of d_out

    k_q<<<Nn, 128>>>(x, w);
    k_gemm<<<dim3(Nn / 128, Nn / 128), 256>>>(x, w, b, G);
    k_rowsum<<<Nn, 256>>>(G);
    k_lanczos<<<NB, NT>>>(G);
    k_tridiag<<<1, 32>>>();
    k_assemble<<<Nn / 256, 256>>>();
    k_rq<<<Nn, 256>>>(G);
    k_final<<<1, 1024>>>(out);
}

// round 11
// speedup vs baseline: 2.0544x; 1.1102x over previous
#include <cuda_runtime.h>
#include <cuda_bf16.h>
#include <math.h>

#define Nn 2048
#define Dd 512
#define M_LZ 128
#define NB 148              // persistent blocks (1 CTA/SM)
#define NT 512
#define NWARP ((NB * NT) / 32)   // 2368 global warps
#ifndef SIGN_CONV
#define SIGN_CONV (-1.0)
#endif

// ---------------- device scratch (static; no runtime allocation) -------------
__device__ float g_q[Nn];
__device__ float g_deg[Nn];
__device__ float g_V[(M_LZ + 1) * Nn];   // row 0 = ones/sqrt(N); rows 1..M basis
__device__ float g_LV[(M_LZ + 1) * Nn];  // rows 1..M: L * v_i (normalized)
__device__ float g_w[Nn];                // raw candidate vector w_j
__device__ float g_ub[Nn];               // ubar = L * w_raw
__device__ float g_acc[Nn];              // pass-1 reorth correction accumulator
__device__ float g_c1a[M_LZ + 2];        // pass-1 dots, halves
__device__ float g_c1b[M_LZ + 2];
__device__ float g_c2a[M_LZ + 2];        // pass-2 dots, halves
__device__ float g_c2b[M_LZ + 2];
__device__ float g_alpha[M_LZ + 2];      // T diagonal (1-based)
__device__ float g_beta2[M_LZ + 2];      // ||w entering iter j||^2 (totals)
__device__ float g_b2part[64];           // per-warp ||w||^2 partials (warps 0..63)
__device__ float g_swupart[NB];          // per-block w.ubar partials
__device__ float g_ssumpart[NB];         // per-block sum(ubar) partials
__device__ float g_c1j;                  // c1_j (computed in B, reused in D)
__device__ float g_mean;
__device__ double g_yd[M_LZ];
__device__ float g_fv[Nn];
__device__ float g_z[Nn];
// grid barrier state
__device__ unsigned g_cnt8[8 * 32];      // 8 group counters, 128B apart
__device__ unsigned g_root;
__device__ volatile unsigned g_gen;

// ---------------- reduction helpers ------------------------------------------
__device__ __forceinline__ float warpReduceSumF(float v) {
#pragma unroll
    for (int o = 16; o; o >>= 1) v += __shfl_down_sync(0xffffffffu, v, o);
    return v;
}
__device__ __forceinline__ double warpReduceSumD(double v) {
#pragma unroll
    for (int o = 16; o; o >>= 1) v += __shfl_down_sync(0xffffffffu, v, o);
    return v;
}
__device__ __forceinline__ float blockReduceSumF(float v, float* sh) {
    int lane = threadIdx.x & 31, wid = threadIdx.x >> 5;
    v = warpReduceSumF(v);
    __syncthreads();
    if (lane == 0) sh[wid] = v;
    __syncthreads();
    if (wid == 0) {
        int nw = (blockDim.x + 31) >> 5;
        float s = (lane < nw) ? sh[lane] : 0.f;
        s = warpReduceSumF(s);
        if (lane == 0) sh[0] = s;
    }
    __syncthreads();
    return sh[0];
}
__device__ __forceinline__ double blockReduceSumD(double v, double* sh) {
    int lane = threadIdx.x & 31, wid = threadIdx.x >> 5;
    v = warpReduceSumD(v);
    __syncthreads();
    if (lane == 0) sh[wid] = v;
    __syncthreads();
    if (wid == 0) {
        int nw = (blockDim.x + 31) >> 5;
        double s = (lane < nw) ? sh[lane] : 0.0;
        s = warpReduceSumD(s);
        if (lane == 0) sh[0] = s;
    }
    __syncthreads();
    return sh[0];
}

__device__ __forceinline__ float sigmoidf_(float s) {
    if (s >= 0.f) { float ez = __expf(-s); return 1.f / (1.f + ez); }
    float ez = __expf(s); return ez / (1.f + ez);
}

// ---------------- acq_rel grid barrier (two-level tree) -----------------------
__device__ __forceinline__ unsigned atom_add_acqrel(unsigned* p, unsigned v) {
    unsigned old;
    asm volatile("atom.acq_rel.gpu.global.add.u32 %0, [%1], %2;"
                 : "=r"(old) : "l"(p), "r"(v) : "memory");
    return old;
}
__device__ __forceinline__ void st_release_u32(volatile unsigned* p, unsigned v) {
    asm volatile("st.release.gpu.global.u32 [%0], %1;" :: "l"(p), "r"(v) : "memory");
}
__device__ __forceinline__ unsigned ld_acquire_u32(volatile unsigned* p) {
    unsigned v;
    asm volatile("ld.acquire.gpu.global.u32 %0, [%1];" : "=r"(v) : "l"(p) : "memory");
    return v;
}
__device__ __forceinline__ void gbar() {
    __syncthreads();
    if (threadIdx.x == 0) {
        unsigned gen = *(volatile unsigned*)&g_gen;
        int grp = blockIdx.x & 7;
        unsigned gsz = (unsigned)(NB >> 3) + ((unsigned)grp < (unsigned)(NB & 7) ? 1u : 0u);
        bool rel = false;
        if (atom_add_acqrel(&g_cnt8[grp * 32], 1u) == gsz - 1u) {
            g_cnt8[grp * 32] = 0;
            if (atom_add_acqrel(&g_root, 1u) == 7u) {
                g_root = 0;
                st_release_u32(&g_gen, gen + 1);
                rel = true;
            }
        }
        if (!rel) {
            while (ld_acquire_u32(&g_gen) == gen) __nanosleep(16);
        }
    }
    __syncthreads();
}

// ---------------- q_i = sum_k w_k x_ik^2 -------------------------------------
__global__ void k_q(const float* __restrict__ x, const float* __restrict__ w) {
    __shared__ float sh[4];
    int i = blockIdx.x, tid = threadIdx.x;
    float acc = 0.f;
    for (int k = tid; k < Dd; k += 128) {
        float xv = x[(size_t)i * Dd + k];
        acc = fmaf(w[k] * xv, xv, acc);
    }
    acc = blockReduceSumF(acc, sh);
    if (tid == 0) g_q[i] = acc;
}

// ---------------- G = sigmoid(q_i + q_j - 2*X diag(w) X^T + b) ---------------
__global__ void k_gemm(const float* __restrict__ x, const float* __restrict__ w,
                       const float* __restrict__ bptr, float* __restrict__ G) {
    __shared__ float As[16][132];
    __shared__ float Bs[16][132];
    int bm = blockIdx.y * 128, bn = blockIdx.x * 128;
    int tid = threadIdx.x;
    int tx = tid & 15, ty = tid >> 4;
    float acc[8][8];
#pragma unroll
    for (int i = 0; i < 8; i++)
#pragma unroll
        for (int j = 0; j < 8; j++) acc[i][j] = 0.f;

    for (int k0 = 0; k0 < Dd; k0 += 16) {
#pragma unroll
        for (int s = 0; s < 8; s++) {
            int li = tid + s * 256;
            int r = li >> 4, kk = li & 15;
            As[kk][r] = x[(size_t)(bm + r) * Dd + k0 + kk] * w[k0 + kk];
            Bs[kk][r] = x[(size_t)(bn + r) * Dd + k0 + kk];
        }
        __syncthreads();
#pragma unroll
        for (int kk = 0; kk < 16; kk++) {
            float a[8], bb[8];
#pragma unroll
            for (int i = 0; i < 8; i++) a[i] = As[kk][ty * 8 + i];
#pragma unroll
            for (int j = 0; j < 8; j++) bb[j] = Bs[kk][tx * 8 + j];
#pragma unroll
            for (int i = 0; i < 8; i++)
#pragma unroll
                for (int j = 0; j < 8; j++) acc[i][j] = fmaf(a[i], bb[j], acc[i][j]);
        }
        __syncthreads();
    }
    float bv = bptr[0];
#pragma unroll
    for (int i = 0; i < 8; i++) {
        int row = bm + ty * 8 + i;
        float qi = g_q[row] + bv;
#pragma unroll
        for (int j = 0; j < 8; j += 4) {
            int col = bn + tx * 8 + j;
            float4 o;
            o.x = sigmoidf_(qi + g_q[col + 0] - 2.f * acc[i][j + 0]);
            o.y = sigmoidf_(qi + g_q[col + 1] - 2.f * acc[i][j + 1]);
            o.z = sigmoidf_(qi + g_q[col + 2] - 2.f * acc[i][j + 2]);
            o.w = sigmoidf_(qi + g_q[col + 3] - 2.f * acc[i][j + 3]);
            *reinterpret_cast<float4*>(&G[(size_t)row * Nn + col]) = o;
        }
    }
}

// ---------------- degree = row sums of G -------------------------------------
__global__ void k_rowsum(const float* __restrict__ G) {
    __shared__ float sh[8];
    int i = blockIdx.x, tid = threadIdx.x;
    const float* row = G + (size_t)i * Nn;
    float acc = 0.f;
    for (int t = tid; t < Nn; t += 256) acc += row[t];
    acc = blockReduceSumF(acc, sh);
    if (tid == 0) g_deg[i] = acc;
}

// ---------------- persistent Lanczos: 4 barriers/iter, no serialized atomics --
__global__ void __launch_bounds__(NT) k_lanczos(const float* __restrict__ G) {
    const int tid = threadIdx.x;
    const int bid = blockIdx.x;
    const int gid = bid * NT + tid;
    const int gw = gid >> 5, lane = gid & 31;
    const int wib = tid >> 5;              // warp in block (0..15)
    const int stripe = gid >> 11;          // 0..36
    const int selem = gid & (Nn - 1);
    const float c0 = rsqrtf((float)Nn);

    __shared__ float s_wu16[16], s_sum16[16];

    // ---- init: V0 = ones*c0, zero acc, v1 = hash - mean
    float r = 0.f;
    if (gid < Nn) {
        unsigned u = (unsigned)(gid + 1) * 2654435761u;
        u ^= u >> 16; u *= 2246822519u; u ^= u >> 13; u *= 3266489917u; u ^= u >> 16;
        r = (float)(u & 0xFFFFFFu) * (1.f / 16777216.f) - 0.5f;
        g_V[gid] = c0;
        g_acc[gid] = 0.f;
    }
    if (gid == 0) g_mean = 0.f;
    gbar();
    if (gw < Nn / 32) {
        float s = warpReduceSumF(r);
        if (lane == 0) atomicAdd(&g_mean, s);
    }
    gbar();
    if (gid < Nn) g_w[gid] = r - g_mean * (1.f / (float)Nn);
    gbar();

    for (int j = 1; j <= M_LZ; j++) {
        // ==== Phase A: beta2 partials; dots1 (split halves); matvec + wu/sum partials
        if (gid < Nn) {
            float wv = g_w[gid];
            float p = warpReduceSumF(wv * wv);
            if (lane == 0) g_b2part[gw] = p;
        }
        {
            float lwu = 0.f, lsum = 0.f;
            const int nDotWarp = 2 * (j - 1);
            if (gw < nDotWarp) {
                int i = 1 + (gw >> 1);
                int base = (gw & 1) * (Nn / 8);   // float4 index offset (1024 floats)
                const float4* lv = reinterpret_cast<const float4*>(g_LV + (size_t)i * Nn) + base;
                const float4* w4 = reinterpret_cast<const float4*>(g_w) + base;
                float acc = 0.f;
#pragma unroll 4
                for (int t = lane; t < Nn / 8; t += 32) {
                    float4 a = lv[t], bq = w4[t];
                    acc += a.x * bq.x + a.y * bq.y + a.z * bq.z + a.w * bq.w;
                }
                acc = warpReduceSumF(acc);
                if (lane == 0) { if (gw & 1) g_c1b[i] = acc; else g_c1a[i] = acc; }
            } else {
                int row = gw - nDotWarp;
                if (row < Nn) {
                    const float4* Gr = reinterpret_cast<const float4*>(G + (size_t)row * Nn);
                    const float4* w4 = reinterpret_cast<const float4*>(g_w);
                    float acc = 0.f;
#pragma unroll 4
                    for (int t = lane; t < Nn / 4; t += 32) {
                        float4 a = Gr[t], bq = w4[t];
                        acc += a.x * bq.x + a.y * bq.y + a.z * bq.z + a.w * bq.w;
                    }
                    acc = warpReduceSumF(acc);
                    if (lane == 0) {
                        float ub = g_deg[row] * g_w[row] - acc;
                        g_ub[row] = ub;
                        lwu = g_w[row] * ub;
                        lsum = ub;
                    }
                }
            }
            if (lane == 0) { s_wu16[wib] = lwu; s_sum16[wib] = lsum; }
        }
        __syncthreads();
        if (tid == 0) {
            float a0 = 0.f, a1 = 0.f;
#pragma unroll
            for (int k = 0; k < 16; k++) { a0 += s_wu16[k]; a1 += s_sum16[k]; }
            g_swupart[bid] = a0;
            g_ssumpart[bid] = a1;
        }
        gbar();

        // ==== Phase B: striped sub1 into acc; stripe0 commits V[j], LV[j]
        if (stripe < 32) {
            // every warp computes beta2 total (64 partials) redundantly
            float b2l = g_b2part[lane] + g_b2part[lane + 32];
            b2l = warpReduceSumF(b2l);
            float b2 = __shfl_sync(0xffffffffu, b2l, 0);
            float invb = rsqrtf(fmaxf(b2, 1e-30f));
            int t = selem;
            float part = 0.f;
#pragma unroll 4
            for (int i = 1 + stripe; i < j; i += 32)
                part = fmaf((g_c1a[i] + g_c1b[i]) * invb, g_V[(size_t)i * Nn + t], part);
            if (stripe == 0) {
                // stripe-0 warps also need swu/ssum totals (148 partials each)
                float swl = 0.f, ssl = 0.f;
                for (int k = lane; k < NB; k += 32) { swl += g_swupart[k]; ssl += g_ssumpart[k]; }
                swl = warpReduceSumF(swl);
                ssl = warpReduceSumF(ssl);
                float swu = __shfl_sync(0xffffffffu, swl, 0);
                float ssum = __shfl_sync(0xffffffffu, ssl, 0);
                float c1j = swu * invb * invb;
                float a0 = c0 * c0 * ssum * invb;
                float wv = g_w[t];
                float vj = wv * invb;
                float uv = g_ub[t] * invb;
                g_V[(size_t)j * Nn + t] = vj;
                g_LV[(size_t)j * Nn + t] = uv;
                part += fmaf(c1j, vj, a0);
                if (gid == 0) { g_beta2[j] = b2; g_c1j = c1j; }
            }
            if (part != 0.f) atomicAdd(&g_acc[t], part);
        }
        gbar();

        // ==== Phase C: dots2 split halves vs (LV[j]-acc); next warps seed w=u
        {
            const int nd = 2 * (j + 1);
            if (gw < nd) {
                int i = gw >> 1;
                int base = (gw & 1) * (Nn / 8);
                const float4* lvj = reinterpret_cast<const float4*>(g_LV + (size_t)j * Nn) + base;
                const float4* ac4 = reinterpret_cast<const float4*>(g_acc) + base;
                const float4* vi = reinterpret_cast<const float4*>(g_V + (size_t)i * Nn) + base;
                float acc = 0.f;
#pragma unroll 4
                for (int t = lane; t < Nn / 8; t += 32) {
                    float4 a = vi[t], u0 = lvj[t], a4 = ac4[t];
                    acc += a.x * (u0.x - a4.x) + a.y * (u0.y - a4.y)
                         + a.z * (u0.z - a4.z) + a.w * (u0.w - a4.w);
                }
                acc = warpReduceSumF(acc);
                if (lane == 0) { if (gw & 1) g_c2b[i] = acc; else g_c2a[i] = acc; }
            } else if (gw < nd + 64) {
                int t = (gw - nd) * 32 + lane;
                g_w[t] = g_LV[(size_t)j * Nn + t] - g_acc[t];
            }
        }
        gbar();

        // ==== Phase D: striped sub2 into w; stripe32 zeroes acc; alpha
        if (stripe < 32) {
            int t = selem;
            float part = 0.f;
#pragma unroll 4
            for (int i = stripe; i <= j; i += 32)
                part = fmaf(g_c2a[i] + g_c2b[i], g_V[(size_t)i * Nn + t], part);
            if (part != 0.f) atomicAdd(&g_w[t], -part);
        } else if (stripe == 32) {
            g_acc[selem] = 0.f;
        }
        if (gid == 0) g_alpha[j] = g_c1j + g_c2a[j] + g_c2b[j];
        gbar();
    }
}

// ---------------- smallest eigenpair of T (m tridiagonal), one warp ----------
__global__ void k_tridiag() {
    __shared__ double aa[M_LZ], bb2[M_LZ], bb[M_LZ];
    __shared__ double dw[M_LZ], ew[M_LZ], fw[M_LZ], yv[M_LZ], rv[M_LZ];
    __shared__ double sx[32];
    __shared__ int scnt[32];
    __shared__ double slo, shi;
    int lane = threadIdx.x;
    for (int i = lane; i < M_LZ; i += 32) {
        aa[i] = (double)g_alpha[i + 1];
        double b2 = (i < M_LZ - 1) ? (double)g_beta2[i + 2] : 0.0;
        bb2[i] = b2;
        bb[i] = sqrt(b2);
    }
    __syncwarp();
    if (lane == 0) {
        double lo = 1e300, hi = -1e300;
        for (int i = 0; i < M_LZ; i++) {
            double bl = (i > 0) ? bb[i - 1] : 0.0;
            double br = (i < M_LZ - 1) ? bb[i] : 0.0;
            lo = fmin(lo, aa[i] - bl - br);
            hi = fmax(hi, aa[i] + bl + br);
        }
        slo = lo - 1.0; shi = hi + 1.0;
    }
    __syncwarp();
    for (int round = 0; round < 8; round++) {
        double lo = slo, hi = shi;
        double x = lo + (hi - lo) * (double)(lane + 1) * (1.0 / 33.0);
        double d = aa[0] - x;
        int cnt = (d < 0.0);
        for (int i = 1; i < M_LZ; i++) {
            if (fabs(d) < 1e-280) d = (d < 0.0 ? -1e-280 : 1e-280);
            d = aa[i] - x - bb2[i - 1] / d;
            cnt += (d < 0.0);
        }
        sx[lane] = x; scnt[lane] = cnt;
        __syncwarp();
        if (lane == 0) {
            double nlo = lo, nhi = hi;
            int k = 0;
            while (k < 32 && scnt[k] < 1) k++;
            if (k < 32) { nhi = sx[k]; if (k > 0) nlo = sx[k - 1]; }
            else        { nlo = sx[31]; }
            slo = nlo; shi = nhi;
        }
        __syncwarp();
    }
    double th = 0.5 * (slo + shi);
    if (lane == 0) {
        for (int i = 0; i < M_LZ; i++) rv[i] = 1.0;
        for (int it = 0; it < 3; it++) {
            for (int i = 0; i < M_LZ; i++) {
                dw[i] = aa[i] - th;
                ew[i] = (i < M_LZ - 1) ? bb[i] : 0.0;
                fw[i] = 0.0;
                yv[i] = rv[i];
            }
            for (int i = 0; i < M_LZ - 1; i++) {
                double s = bb[i];
                if (fabs(s) > fabs(dw[i])) {
                    double od = dw[i], oe = ew[i], of = fw[i];
                    dw[i] = s;       ew[i] = dw[i + 1]; fw[i] = ew[i + 1];
                    s = od;          dw[i + 1] = oe;    ew[i + 1] = of;
                    double ry = yv[i]; yv[i] = yv[i + 1]; yv[i + 1] = ry;
                }
                double p = dw[i];
                if (fabs(p) < 1e-280) { p = (p < 0.0 ? -1e-280 : 1e-280); dw[i] = p; }
                double m = s / p;
                dw[i + 1] -= m * ew[i];
                ew[i + 1] -= m * fw[i];
                yv[i + 1] -= m * yv[i];
            }
            for (int i = M_LZ - 1; i >= 0; i--) {
                double v = yv[i];
                if (i + 1 < M_LZ) v -= ew[i] * yv[i + 1];
                if (i + 2 < M_LZ) v -= fw[i] * yv[i + 2];
                double p = dw[i];
                if (fabs(p) < 1e-280) p = (p < 0.0 ? -1e-280 : 1e-280);
                yv[i] = v / p;
            }
            double n2 = 0.0;
            for (int i = 0; i < M_LZ; i++) n2 += yv[i] * yv[i];
            double inv = 1.0 / sqrt(n2);
            for (int i = 0; i < M_LZ; i++) rv[i] = yv[i] * inv;
        }
        for (int i = 0; i < M_LZ; i++) g_yd[i] = rv[i];
    }
}

// ---------------- fv = sum_r y_{r-1} V[r] -------------------------------------
__global__ void k_assemble() {
    int t = blockIdx.x * 256 + threadIdx.x;
    float acc = 0.f;
    for (int rr = 1; rr <= M_LZ; rr++)
        acc = fmaf((float)g_yd[rr - 1], g_V[(size_t)rr * Nn + t], acc);
    g_fv[t] = acc;
}

// ---------------- z = L * fv (fp32) -------------------------------------------
__global__ void k_rq(const float* __restrict__ G) {
    __shared__ float sh[8];
    int i = blockIdx.x, tid = threadIdx.x;
    const float* row = G + (size_t)i * Nn;
    float acc = 0.f;
    for (int t = tid; t < Nn; t += 256) acc = fmaf(row[t], g_fv[t], acc);
    acc = blockReduceSumF(acc, sh);
    if (tid == 0) g_z[i] = g_deg[i] * g_fv[i] - acc;
}

// ---------------- value = fv.z / fv.fv; normalize + sign + write --------------
__global__ void k_final(float* __restrict__ out) {
    __shared__ double sh[32];
    __shared__ float sabs[32];
    __shared__ int sidx[32];
    __shared__ double ssign;
    int tid = threadIdx.x;
    double a = (double)g_fv[tid], b = (double)g_fv[tid + 1024];
    double num = blockReduceSumD(a * (double)g_z[tid] + b * (double)g_z[tid + 1024], sh);
    double den = blockReduceSumD(a * a + b * b, sh);
    float bav; int bix;
    float fa = (float)fabs(a), fb = (float)fabs(b);
    if (fa >= fb) { bav = fa; bix = tid; }
    else          { bav = fb; bix = tid + 1024; }
#pragma unroll
    for (int o = 16; o; o >>= 1) {
        float ov = __shfl_down_sync(0xffffffffu, bav, o);
        int   oi = __shfl_down_sync(0xffffffffu, bix, o);
        if (ov > bav || (ov == bav && oi < bix)) { bav = ov; bix = oi; }
    }
    int lane = tid & 31, wid = tid >> 5;
    if (lane == 0) { sabs[wid] = bav; sidx[wid] = bix; }
    __syncthreads();
    if (tid == 0) {
        float bv = sabs[0]; int bi = sidx[0];
        for (int i = 1; i < 32; i++)
            if (sabs[i] > bv || (sabs[i] == bv && sidx[i] < bi)) { bv = sabs[i]; bi = sidx[i]; }
        ssign = (g_fv[bi] >= 0.f ? 1.0 : -1.0) * SIGN_CONV;
        out[(size_t)Nn * Nn] = (float)(num / fmax(den, 1e-300));
    }
    __syncthreads();
    double sc = ssign / sqrt(fmax(den, 1e-300));
    size_t base = (size_t)Nn * Nn + 1;
    out[base + tid]        = (float)(a * sc);
    out[base + tid + 1024] = (float)(b * sc);
}

// ---------------- launcher ----------------------------------------------------
extern "C" void kernel_launch(void* const* d_in, const int* in_sizes, int n_in,
                              void* d_out, int out_size) {
    const float* x = (const float*)d_in[0];
    const float* w = (const float*)d_in[1];
    const float* b = (const float*)d_in[2];
    float* out = (float*)d_out;
    float* G = out;   // grouping matrix lives at the front of d_out

    k_q<<<Nn, 128>>>(x, w);
    k_gemm<<<dim3(Nn / 128, Nn / 128), 256>>>(x, w, b, G);
    k_rowsum<<<Nn, 256>>>(G);
    k_lanczos<<<NB, NT>>>(G);
    k_tridiag<<<1, 32>>>();
    k_assemble<<<Nn / 256, 256>>>();
    k_rq<<<Nn, 256>>>(G);
    k_final<<<1, 1024>>>(out);
}

// round 12
// speedup vs baseline: 2.0635x; 1.0045x over previous
#include <cuda_runtime.h>
#include <cuda_bf16.h>
#include <math.h>

#define Nn 2048
#define Dd 512
#define M_LZ 128
#define NB 148              // persistent blocks (1 CTA/SM)
#define NT 512
#define NWARP ((NB * NT) / 32)   // 2368 global warps
#ifndef SIGN_CONV
#define SIGN_CONV (-1.0)
#endif

// ---------------- device scratch (static; no runtime allocation) -------------
__device__ float g_q[Nn];
__device__ float g_deg[Nn];
__device__ float g_V[(M_LZ + 1) * Nn];   // row 0 = ones/sqrt(N); rows 1..M basis
__device__ float g_LV[(M_LZ + 1) * Nn];  // rows 1..M: L * v_i (normalized)
__device__ float g_w[Nn];                // raw candidate vector w_j
__device__ float g_ub[Nn];               // ubar = L * w_raw
__device__ float g_acc[Nn];              // pass-1 reorth correction accumulator
__device__ float g_c1a[M_LZ + 2];        // pass-1 dots, halves
__device__ float g_c1b[M_LZ + 2];
__device__ float g_c2a[M_LZ + 2];        // pass-2 dots, halves
__device__ float g_c2b[M_LZ + 2];
__device__ float g_alpha[M_LZ + 2];      // T diagonal (1-based)
__device__ float g_beta2[M_LZ + 2];      // ||w entering iter j||^2 (totals)
__device__ float g_b2part[64];           // per-warp ||w||^2 partials (warps 0..63)
__device__ float g_swupart[NB];          // per-block w.ubar partials
__device__ float g_ssumpart[NB];         // per-block sum(ubar) partials
__device__ float g_c1j;                  // c1_j (computed in B, reused in D)
__device__ float g_mean;
__device__ double g_yd[M_LZ];
__device__ float g_fv[Nn];
__device__ float g_z[Nn];
// grid barrier state
__device__ unsigned g_cnt8[8 * 32];      // 8 group counters, 128B apart
__device__ unsigned g_root;
__device__ volatile unsigned g_gen;

// ---------------- reduction helpers ------------------------------------------
__device__ __forceinline__ float warpReduceSumF(float v) {
#pragma unroll
    for (int o = 16; o; o >>= 1) v += __shfl_down_sync(0xffffffffu, v, o);
    return v;
}
__device__ __forceinline__ double warpReduceSumD(double v) {
#pragma unroll
    for (int o = 16; o; o >>= 1) v += __shfl_down_sync(0xffffffffu, v, o);
    return v;
}
__device__ __forceinline__ float blockReduceSumF(float v, float* sh) {
    int lane = threadIdx.x & 31, wid = threadIdx.x >> 5;
    v = warpReduceSumF(v);
    __syncthreads();
    if (lane == 0) sh[wid] = v;
    __syncthreads();
    if (wid == 0) {
        int nw = (blockDim.x + 31) >> 5;
        float s = (lane < nw) ? sh[lane] : 0.f;
        s = warpReduceSumF(s);
        if (lane == 0) sh[0] = s;
    }
    __syncthreads();
    return sh[0];
}
__device__ __forceinline__ double blockReduceSumD(double v, double* sh) {
    int lane = threadIdx.x & 31, wid = threadIdx.x >> 5;
    v = warpReduceSumD(v);
    __syncthreads();
    if (lane == 0) sh[wid] = v;
    __syncthreads();
    if (wid == 0) {
        int nw = (blockDim.x + 31) >> 5;
        double s = (lane < nw) ? sh[lane] : 0.0;
        s = warpReduceSumD(s);
        if (lane == 0) sh[0] = s;
    }
    __syncthreads();
    return sh[0];
}

__device__ __forceinline__ float sigmoidf_(float s) {
    if (s >= 0.f) { float ez = __expf(-s); return 1.f / (1.f + ez); }
    float ez = __expf(s); return ez / (1.f + ez);
}

// ---------------- acq_rel grid barrier (two-level tree) -----------------------
__device__ __forceinline__ unsigned atom_add_acqrel(unsigned* p, unsigned v) {
    unsigned old;
    asm volatile("atom.acq_rel.gpu.global.add.u32 %0, [%1], %2;"
                 : "=r"(old) : "l"(p), "r"(v) : "memory");
    return old;
}
__device__ __forceinline__ void st_release_u32(volatile unsigned* p, unsigned v) {
    asm volatile("st.release.gpu.global.u32 [%0], %1;" :: "l"(p), "r"(v) : "memory");
}
__device__ __forceinline__ unsigned ld_acquire_u32(volatile unsigned* p) {
    unsigned v;
    asm volatile("ld.acquire.gpu.global.u32 %0, [%1];" : "=r"(v) : "l"(p) : "memory");
    return v;
}
__device__ __forceinline__ void gbar() {
    __syncthreads();
    if (threadIdx.x == 0) {
        unsigned gen = *(volatile unsigned*)&g_gen;
        int grp = blockIdx.x & 7;
        unsigned gsz = (unsigned)(NB >> 3) + ((unsigned)grp < (unsigned)(NB & 7) ? 1u : 0u);
        bool rel = false;
        if (atom_add_acqrel(&g_cnt8[grp * 32], 1u) == gsz - 1u) {
            g_cnt8[grp * 32] = 0;
            if (atom_add_acqrel(&g_root, 1u) == 7u) {
                g_root = 0;
                st_release_u32(&g_gen, gen + 1);
                rel = true;
            }
        }
        if (!rel) {
            while (ld_acquire_u32(&g_gen) == gen) __nanosleep(16);
        }
    }
    __syncthreads();
}

// ---------------- q_i = sum_k w_k x_ik^2 -------------------------------------
__global__ void k_q(const float* __restrict__ x, const float* __restrict__ w) {
    __shared__ float sh[4];
    int i = blockIdx.x, tid = threadIdx.x;
    float acc = 0.f;
    for (int k = tid; k < Dd; k += 128) {
        float xv = x[(size_t)i * Dd + k];
        acc = fmaf(w[k] * xv, xv, acc);
    }
    acc = blockReduceSumF(acc, sh);
    if (tid == 0) g_q[i] = acc;
}

// ---------------- G = sigmoid(q_i + q_j - 2*X diag(w) X^T + b) ---------------
__global__ void k_gemm(const float* __restrict__ x, const float* __restrict__ w,
                       const float* __restrict__ bptr, float* __restrict__ G) {
    __shared__ float As[16][132];
    __shared__ float Bs[16][132];
    int bm = blockIdx.y * 128, bn = blockIdx.x * 128;
    int tid = threadIdx.x;
    int tx = tid & 15, ty = tid >> 4;
    float acc[8][8];
#pragma unroll
    for (int i = 0; i < 8; i++)
#pragma unroll
        for (int j = 0; j < 8; j++) acc[i][j] = 0.f;

    for (int k0 = 0; k0 < Dd; k0 += 16) {
#pragma unroll
        for (int s = 0; s < 8; s++) {
            int li = tid + s * 256;
            int r = li >> 4, kk = li & 15;
            As[kk][r] = x[(size_t)(bm + r) * Dd + k0 + kk] * w[k0 + kk];
            Bs[kk][r] = x[(size_t)(bn + r) * Dd + k0 + kk];
        }
        __syncthreads();
#pragma unroll
        for (int kk = 0; kk < 16; kk++) {
            float a[8], bb[8];
#pragma unroll
            for (int i = 0; i < 8; i++) a[i] = As[kk][ty * 8 + i];
#pragma unroll
            for (int j = 0; j < 8; j++) bb[j] = Bs[kk][tx * 8 + j];
#pragma unroll
            for (int i = 0; i < 8; i++)
#pragma unroll
                for (int j = 0; j < 8; j++) acc[i][j] = fmaf(a[i], bb[j], acc[i][j]);
        }
        __syncthreads();
    }
    float bv = bptr[0];
#pragma unroll
    for (int i = 0; i < 8; i++) {
        int row = bm + ty * 8 + i;
        float qi = g_q[row] + bv;
#pragma unroll
        for (int j = 0; j < 8; j += 4) {
            int col = bn + tx * 8 + j;
            float4 o;
            o.x = sigmoidf_(qi + g_q[col + 0] - 2.f * acc[i][j + 0]);
            o.y = sigmoidf_(qi + g_q[col + 1] - 2.f * acc[i][j + 1]);
            o.z = sigmoidf_(qi + g_q[col + 2] - 2.f * acc[i][j + 2]);
            o.w = sigmoidf_(qi + g_q[col + 3] - 2.f * acc[i][j + 3]);
            *reinterpret_cast<float4*>(&G[(size_t)row * Nn + col]) = o;
        }
    }
}

// ---------------- persistent Lanczos: 4 barriers/iter, shared-staged w --------
__global__ void __launch_bounds__(NT) k_lanczos(const float* __restrict__ G) {
    const int tid = threadIdx.x;
    const int bid = blockIdx.x;
    const int gid = bid * NT + tid;
    const int gw = gid >> 5, lane = gid & 31;
    const int wib = tid >> 5;              // warp in block (0..15)
    const int stripe = gid >> 11;          // 0..36
    const int selem = gid & (Nn - 1);
    const float c0 = rsqrtf((float)Nn);

    __shared__ float s_wu16[16], s_sum16[16];
    __shared__ float s_w[Nn];              // staged w (full vector, 8KB)
    float4* s_w4 = reinterpret_cast<float4*>(s_w);

    // ---- init: V0 = ones*c0, zero acc, v1 = hash - mean; fold rowsum -> deg
    float r = 0.f;
    if (gid < Nn) {
        unsigned u = (unsigned)(gid + 1) * 2654435761u;
        u ^= u >> 16; u *= 2246822519u; u ^= u >> 13; u *= 3266489917u; u ^= u >> 16;
        r = (float)(u & 0xFFFFFFu) * (1.f / 16777216.f) - 0.5f;
        g_V[gid] = c0;
        g_acc[gid] = 0.f;
    }
    if (gid == 0) g_mean = 0.f;
    if (gw < Nn) {      // degree: one warp per row
        const float4* Gr = reinterpret_cast<const float4*>(G + (size_t)gw * Nn);
        float acc = 0.f;
#pragma unroll 4
        for (int t = lane; t < Nn / 4; t += 32) {
            float4 a = Gr[t];
            acc += a.x + a.y + a.z + a.w;
        }
        acc = warpReduceSumF(acc);
        if (lane == 0) g_deg[gw] = acc;
    }
    gbar();
    if (gw < Nn / 32) {
        float s = warpReduceSumF(r);
        if (lane == 0) atomicAdd(&g_mean, s);
    }
    gbar();
    if (gid < Nn) g_w[gid] = r - g_mean * (1.f / (float)Nn);
    gbar();

    for (int j = 1; j <= M_LZ; j++) {
        // ==== Phase A: stage w; beta2 partials; dots1 halves; matvec + partials
        s_w4[tid] = reinterpret_cast<const float4*>(g_w)[tid];   // 512 x float4 = 2048
        __syncthreads();
        if (gid < Nn) {
            float wv = s_w[gid];
            float p = warpReduceSumF(wv * wv);
            if (lane == 0) g_b2part[gw] = p;
        }
        {
            float lwu = 0.f, lsum = 0.f;
            const int nDotWarp = 2 * (j - 1);
            if (gw < nDotWarp) {
                int i = 1 + (gw >> 1);
                int base = (gw & 1) * (Nn / 8);   // float4 index offset
                const float4* lv = reinterpret_cast<const float4*>(g_LV + (size_t)i * Nn) + base;
                const float4* w4 = s_w4 + base;
                float acc = 0.f;
#pragma unroll 4
                for (int t = lane; t < Nn / 8; t += 32) {
                    float4 a = lv[t], bq = w4[t];
                    acc += a.x * bq.x + a.y * bq.y + a.z * bq.z + a.w * bq.w;
                }
                acc = warpReduceSumF(acc);
                if (lane == 0) { if (gw & 1) g_c1b[i] = acc; else g_c1a[i] = acc; }
            } else {
                int row = gw - nDotWarp;
                if (row < Nn) {
                    const float4* Gr = reinterpret_cast<const float4*>(G + (size_t)row * Nn);
                    float acc = 0.f;
#pragma unroll 4
                    for (int t = lane; t < Nn / 4; t += 32) {
                        float4 a = Gr[t], bq = s_w4[t];
                        acc += a.x * bq.x + a.y * bq.y + a.z * bq.z + a.w * bq.w;
                    }
                    acc = warpReduceSumF(acc);
                    if (lane == 0) {
                        float ub = g_deg[row] * s_w[row] - acc;
                        g_ub[row] = ub;
                        lwu = s_w[row] * ub;
                        lsum = ub;
                    }
                }
            }
            if (lane == 0) { s_wu16[wib] = lwu; s_sum16[wib] = lsum; }
        }
        __syncthreads();
        if (tid == 0) {
            float a0 = 0.f, a1 = 0.f;
#pragma unroll
            for (int k = 0; k < 16; k++) { a0 += s_wu16[k]; a1 += s_sum16[k]; }
            g_swupart[bid] = a0;
            g_ssumpart[bid] = a1;
        }
        gbar();

        // ==== Phase B: striped sub1 into acc; stripe0 commits V[j], LV[j]
        if (stripe < 32) {
            float b2l = g_b2part[lane] + g_b2part[lane + 32];
            b2l = warpReduceSumF(b2l);
            float b2 = __shfl_sync(0xffffffffu, b2l, 0);
            float invb = rsqrtf(fmaxf(b2, 1e-30f));
            int t = selem;
            float part = 0.f;
#pragma unroll 4
            for (int i = 1 + stripe; i < j; i += 32)
                part = fmaf((g_c1a[i] + g_c1b[i]) * invb, g_V[(size_t)i * Nn + t], part);
            if (stripe == 0) {
                float swl = 0.f, ssl = 0.f;
                for (int k = lane; k < NB; k += 32) { swl += g_swupart[k]; ssl += g_ssumpart[k]; }
                swl = warpReduceSumF(swl);
                ssl = warpReduceSumF(ssl);
                float swu = __shfl_sync(0xffffffffu, swl, 0);
                float ssum = __shfl_sync(0xffffffffu, ssl, 0);
                float c1j = swu * invb * invb;
                float a0 = c0 * c0 * ssum * invb;
                float wv = g_w[t];
                float vj = wv * invb;
                float uv = g_ub[t] * invb;
                g_V[(size_t)j * Nn + t] = vj;
                g_LV[(size_t)j * Nn + t] = uv;
                part += fmaf(c1j, vj, a0);
                if (gid == 0) { g_beta2[j] = b2; g_c1j = c1j; }
            }
            if (part != 0.f) atomicAdd(&g_acc[t], part);
        }
        gbar();

        // ==== Phase C: dots2 split halves vs (LV[j]-acc); next warps seed w=u
        {
            const int nd = 2 * (j + 1);
            if (gw < nd) {
                int i = gw >> 1;
                int base = (gw & 1) * (Nn / 8);
                const float4* lvj = reinterpret_cast<const float4*>(g_LV + (size_t)j * Nn) + base;
                const float4* ac4 = reinterpret_cast<const float4*>(g_acc) + base;
                const float4* vi = reinterpret_cast<const float4*>(g_V + (size_t)i * Nn) + base;
                float acc = 0.f;
#pragma unroll 4
                for (int t = lane; t < Nn / 8; t += 32) {
                    float4 a = vi[t], u0 = lvj[t], a4 = ac4[t];
                    acc += a.x * (u0.x - a4.x) + a.y * (u0.y - a4.y)
                         + a.z * (u0.z - a4.z) + a.w * (u0.w - a4.w);
                }
                acc = warpReduceSumF(acc);
                if (lane == 0) { if (gw & 1) g_c2b[i] = acc; else g_c2a[i] = acc; }
            } else if (gw < nd + 64) {
                int t = (gw - nd) * 32 + lane;
                g_w[t] = g_LV[(size_t)j * Nn + t] - g_acc[t];
            }
        }
        gbar();

        // ==== Phase D: striped sub2 into w; stripe32 zeroes acc; alpha
        if (stripe < 32) {
            int t = selem;
            float part = 0.f;
#pragma unroll 4
            for (int i = stripe; i <= j; i += 32)
                part = fmaf(g_c2a[i] + g_c2b[i], g_V[(size_t)i * Nn + t], part);
            if (part != 0.f) atomicAdd(&g_w[t], -part);
        } else if (stripe == 32) {
            g_acc[selem] = 0.f;
        }
        if (gid == 0) g_alpha[j] = g_c1j + g_c2a[j] + g_c2b[j];
        gbar();
    }
}

// ---------------- smallest eigenpair of T (m tridiagonal), one warp ----------
__global__ void k_tridiag() {
    __shared__ double aa[M_LZ], bb2[M_LZ], bb[M_LZ];
    __shared__ double dw[M_LZ], ew[M_LZ], fw[M_LZ], yv[M_LZ], rv[M_LZ];
    __shared__ double sx[32];
    __shared__ int scnt[32];
    __shared__ double slo, shi;
    int lane = threadIdx.x;
    for (int i = lane; i < M_LZ; i += 32) {
        aa[i] = (double)g_alpha[i + 1];
        double b2 = (i < M_LZ - 1) ? (double)g_beta2[i + 2] : 0.0;
        bb2[i] = b2;
        bb[i] = sqrt(b2);
    }
    __syncwarp();
    if (lane == 0) {
        double lo = 1e300, hi = -1e300;
        for (int i = 0; i < M_LZ; i++) {
            double bl = (i > 0) ? bb[i - 1] : 0.0;
            double br = (i < M_LZ - 1) ? bb[i] : 0.0;
            lo = fmin(lo, aa[i] - bl - br);
            hi = fmax(hi, aa[i] + bl + br);
        }
        slo = lo - 1.0; shi = hi + 1.0;
    }
    __syncwarp();
    for (int round = 0; round < 8; round++) {
        double lo = slo, hi = shi;
        double x = lo + (hi - lo) * (double)(lane + 1) * (1.0 / 33.0);
        double d = aa[0] - x;
        int cnt = (d < 0.0);
        for (int i = 1; i < M_LZ; i++) {
            if (fabs(d) < 1e-280) d = (d < 0.0 ? -1e-280 : 1e-280);
            d = aa[i] - x - bb2[i - 1] / d;
            cnt += (d < 0.0);
        }
        sx[lane] = x; scnt[lane] = cnt;
        __syncwarp();
        if (lane == 0) {
            double nlo = lo, nhi = hi;
            int k = 0;
            while (k < 32 && scnt[k] < 1) k++;
            if (k < 32) { nhi = sx[k]; if (k > 0) nlo = sx[k - 1]; }
            else        { nlo = sx[31]; }
            slo = nlo; shi = nhi;
        }
        __syncwarp();
    }
    double th = 0.5 * (slo + shi);
    if (lane == 0) {
        for (int i = 0; i < M_LZ; i++) rv[i] = 1.0;
        for (int it = 0; it < 3; it++) {
            for (int i = 0; i < M_LZ; i++) {
                dw[i] = aa[i] - th;
                ew[i] = (i < M_LZ - 1) ? bb[i] : 0.0;
                fw[i] = 0.0;
                yv[i] = rv[i];
            }
            for (int i = 0; i < M_LZ - 1; i++) {
                double s = bb[i];
                if (fabs(s) > fabs(dw[i])) {
                    double od = dw[i], oe = ew[i], of = fw[i];
                    dw[i] = s;       ew[i] = dw[i + 1]; fw[i] = ew[i + 1];
                    s = od;          dw[i + 1] = oe;    ew[i + 1] = of;
                    double ry = yv[i]; yv[i] = yv[i + 1]; yv[i + 1] = ry;
                }
                double p = dw[i];
                if (fabs(p) < 1e-280) { p = (p < 0.0 ? -1e-280 : 1e-280); dw[i] = p; }
                double m = s / p;
                dw[i + 1] -= m * ew[i];
                ew[i + 1] -= m * fw[i];
                yv[i + 1] -= m * yv[i];
            }
            for (int i = M_LZ - 1; i >= 0; i--) {
                double v = yv[i];
                if (i + 1 < M_LZ) v -= ew[i] * yv[i + 1];
                if (i + 2 < M_LZ) v -= fw[i] * yv[i + 2];
                double p = dw[i];
                if (fabs(p) < 1e-280) p = (p < 0.0 ? -1e-280 : 1e-280);
                yv[i] = v / p;
            }
            double n2 = 0.0;
            for (int i = 0; i < M_LZ; i++) n2 += yv[i] * yv[i];
            double inv = 1.0 / sqrt(n2);
            for (int i = 0; i < M_LZ; i++) rv[i] = yv[i] * inv;
        }
        for (int i = 0; i < M_LZ; i++) g_yd[i] = rv[i];
    }
}

// ---------------- fv = sum_r y_{r-1} V[r] -------------------------------------
__global__ void k_assemble() {
    int t = blockIdx.x * 256 + threadIdx.x;
    float acc = 0.f;
    for (int rr = 1; rr <= M_LZ; rr++)
        acc = fmaf((float)g_yd[rr - 1], g_V[(size_t)rr * Nn + t], acc);
    g_fv[t] = acc;
}

// ---------------- z = L * fv (fp32) -------------------------------------------
__global__ void k_rq(const float* __restrict__ G) {
    __shared__ float sh[8];
    int i = blockIdx.x, tid = threadIdx.x;
    const float* row = G + (size_t)i * Nn;
    float acc = 0.f;
    for (int t = tid; t < Nn; t += 256) acc = fmaf(row[t], g_fv[t], acc);
    acc = blockReduceSumF(acc, sh);
    if (tid == 0) g_z[i] = g_deg[i] * g_fv[i] - acc;
}

// ---------------- value = fv.z / fv.fv; normalize + sign + write --------------
__global__ void k_final(float* __restrict__ out) {
    __shared__ double sh[32];
    __shared__ float sabs[32];
    __shared__ int sidx[32];
    __shared__ double ssign;
    int tid = threadIdx.x;
    double a = (double)g_fv[tid], b = (double)g_fv[tid + 1024];
    double num = blockReduceSumD(a * (double)g_z[tid] + b * (double)g_z[tid + 1024], sh);
    double den = blockReduceSumD(a * a + b * b, sh);
    float bav; int bix;
    float fa = (float)fabs(a), fb = (float)fabs(b);
    if (fa >= fb) { bav = fa; bix = tid; }
    else          { bav = fb; bix = tid + 1024; }
#pragma unroll
    for (int o = 16; o; o >>= 1) {
        float ov = __shfl_down_sync(0xffffffffu, bav, o);
        int   oi = __shfl_down_sync(0xffffffffu, bix, o);
        if (ov > bav || (ov == bav && oi < bix)) { bav = ov; bix = oi; }
    }
    int lane = tid & 31, wid = tid >> 5;
    if (lane == 0) { sabs[wid] = bav; sidx[wid] = bix; }
    __syncthreads();
    if (tid == 0) {
        float bv = sabs[0]; int bi = sidx[0];
        for (int i = 1; i < 32; i++)
            if (sabs[i] > bv || (sabs[i] == bv && sidx[i] < bi)) { bv = sabs[i]; bi = sidx[i]; }
        ssign = (g_fv[bi] >= 0.f ? 1.0 : -1.0) * SIGN_CONV;
        out[(size_t)Nn * Nn] = (float)(num / fmax(den, 1e-300));
    }
    __syncthreads();
    double sc = ssign / sqrt(fmax(den, 1e-300));
    size_t base = (size_t)Nn * Nn + 1;
    out[base + tid]        = (float)(a * sc);
    out[base + tid + 1024] = (float)(b * sc);
}

// ---------------- launcher ----------------------------------------------------
extern "C" void kernel_launch(void* const* d_in, const int* in_sizes, int n_in,
                              void* d_out, int out_size) {
    const float* x = (const float*)d_in[0];
    const float* w = (const float*)d_in[1];
    const float* b = (const float*)d_in[2];
    float* out = (float*)d_out;
    float* G = out;   // grouping matrix lives at the front of d_out

    k_q<<<Nn, 128>>>(x, w);
    k_gemm<<<dim3(Nn / 128, Nn / 128), 256>>>(x, w, b, G);
    k_lanczos<<<NB, NT>>>(G);
    k_tridiag<<<1, 32>>>();
    k_assemble<<<Nn / 256, 256>>>();
    k_rq<<<Nn, 256>>>(G);
    k_final<<<1, 1024>>>(out);
}

// round 13
// speedup vs baseline: 2.4731x; 1.1985x over previous
#include <cuda_runtime.h>
#include <cuda_bf16.h>
#include <math.h>

#define Nn 2048
#define Dd 512
#define M_LZ 128
#define NB 148              // persistent blocks (1 CTA/SM)
#define NT 512
#define NWARP ((NB * NT) / 32)   // 2368 global warps
#ifndef SIGN_CONV
#define SIGN_CONV (-1.0)
#endif

// ---------------- device scratch (static; no runtime allocation) -------------
__device__ float g_q[Nn];
__device__ float g_deg[Nn];
__device__ float g_V[(M_LZ + 1) * Nn];   // row 0 = ones/sqrt(N); rows 1..M basis
__device__ float g_LV[(M_LZ + 1) * Nn];  // rows 1..M: L * v_i (normalized)
__device__ float g_w[Nn];                // raw candidate vector w_j
__device__ float g_ub[Nn];               // ubar = L * w_raw
__device__ float g_acc[Nn];              // pass-1 reorth correction accumulator
__device__ float g_c1a[M_LZ + 2];        // pass-1 dots, halves
__device__ float g_c1b[M_LZ + 2];
__device__ float g_c2a[M_LZ + 2];        // pass-2 dots, halves
__device__ float g_c2b[M_LZ + 2];
__device__ float g_alpha[M_LZ + 2];      // T diagonal (1-based)
__device__ float g_beta2[M_LZ + 2];      // ||w entering iter j||^2 (totals)
__device__ float g_b2part[64];           // per-warp ||w||^2 partials (warps 0..63)
__device__ float g_swupart[NB];          // per-block w.ubar partials
__device__ float g_ssumpart[NB];         // per-block sum(ubar) partials
__device__ float g_c1j;                  // c1_j (computed in B, reused in D)
__device__ float g_mean;
__device__ float g_y[M_LZ];              // tridiagonal eigenvector (fp32)
__device__ float g_fv[Nn];
__device__ float g_z[Nn];
// grid barrier state
__device__ unsigned g_cnt8[8 * 32];      // 8 group counters, 128B apart
__device__ unsigned g_root;
__device__ volatile unsigned g_gen;

// ---------------- reduction helpers ------------------------------------------
__device__ __forceinline__ float warpReduceSumF(float v) {
#pragma unroll
    for (int o = 16; o; o >>= 1) v += __shfl_down_sync(0xffffffffu, v, o);
    return v;
}
__device__ __forceinline__ double warpReduceSumD(double v) {
#pragma unroll
    for (int o = 16; o; o >>= 1) v += __shfl_down_sync(0xffffffffu, v, o);
    return v;
}
__device__ __forceinline__ float blockReduceSumF(float v, float* sh) {
    int lane = threadIdx.x & 31, wid = threadIdx.x >> 5;
    v = warpReduceSumF(v);
    __syncthreads();
    if (lane == 0) sh[wid] = v;
    __syncthreads();
    if (wid == 0) {
        int nw = (blockDim.x + 31) >> 5;
        float s = (lane < nw) ? sh[lane] : 0.f;
        s = warpReduceSumF(s);
        if (lane == 0) sh[0] = s;
    }
    __syncthreads();
    return sh[0];
}
__device__ __forceinline__ double blockReduceSumD(double v, double* sh) {
    int lane = threadIdx.x & 31, wid = threadIdx.x >> 5;
    v = warpReduceSumD(v);
    __syncthreads();
    if (lane == 0) sh[wid] = v;
    __syncthreads();
    if (wid == 0) {
        int nw = (blockDim.x + 31) >> 5;
        double s = (lane < nw) ? sh[lane] : 0.0;
        s = warpReduceSumD(s);
        if (lane == 0) sh[0] = s;
    }
    __syncthreads();
    return sh[0];
}

__device__ __forceinline__ float sigmoidf_(float s) {
    if (s >= 0.f) { float ez = __expf(-s); return 1.f / (1.f + ez); }
    float ez = __expf(s); return ez / (1.f + ez);
}

// ---------------- acq_rel grid barrier (two-level tree) -----------------------
__device__ __forceinline__ unsigned atom_add_acqrel(unsigned* p, unsigned v) {
    unsigned old;
    asm volatile("atom.acq_rel.gpu.global.add.u32 %0, [%1], %2;"
                 : "=r"(old) : "l"(p), "r"(v) : "memory");
    return old;
}
__device__ __forceinline__ void st_release_u32(volatile unsigned* p, unsigned v) {
    asm volatile("st.release.gpu.global.u32 [%0], %1;" :: "l"(p), "r"(v) : "memory");
}
__device__ __forceinline__ unsigned ld_acquire_u32(volatile unsigned* p) {
    unsigned v;
    asm volatile("ld.acquire.gpu.global.u32 %0, [%1];" : "=r"(v) : "l"(p) : "memory");
    return v;
}
__device__ __forceinline__ void gbar() {
    __syncthreads();
    if (threadIdx.x == 0) {
        unsigned gen = *(volatile unsigned*)&g_gen;
        int grp = blockIdx.x & 7;
        unsigned gsz = (unsigned)(NB >> 3) + ((unsigned)grp < (unsigned)(NB & 7) ? 1u : 0u);
        bool rel = false;
        if (atom_add_acqrel(&g_cnt8[grp * 32], 1u) == gsz - 1u) {
            g_cnt8[grp * 32] = 0;
            if (atom_add_acqrel(&g_root, 1u) == 7u) {
                g_root = 0;
                st_release_u32(&g_gen, gen + 1);
                rel = true;
            }
        }
        if (!rel) {
            while (ld_acquire_u32(&g_gen) == gen) __nanosleep(16);
        }
    }
    __syncthreads();
}

// ---------------- q_i = sum_k w_k x_ik^2 -------------------------------------
__global__ void k_q(const float* __restrict__ x, const float* __restrict__ w) {
    __shared__ float sh[4];
    int i = blockIdx.x, tid = threadIdx.x;
    float acc = 0.f;
    for (int k = tid; k < Dd; k += 128) {
        float xv = x[(size_t)i * Dd + k];
        acc = fmaf(w[k] * xv, xv, acc);
    }
    acc = blockReduceSumF(acc, sh);
    if (tid == 0) g_q[i] = acc;
}

// ---------------- G = sigmoid(q_i + q_j - 2*X diag(w) X^T + b) ---------------
__global__ void k_gemm(const float* __restrict__ x, const float* __restrict__ w,
                       const float* __restrict__ bptr, float* __restrict__ G) {
    __shared__ float As[16][132];
    __shared__ float Bs[16][132];
    int bm = blockIdx.y * 128, bn = blockIdx.x * 128;
    int tid = threadIdx.x;
    int tx = tid & 15, ty = tid >> 4;
    float acc[8][8];
#pragma unroll
    for (int i = 0; i < 8; i++)
#pragma unroll
        for (int j = 0; j < 8; j++) acc[i][j] = 0.f;

    for (int k0 = 0; k0 < Dd; k0 += 16) {
#pragma unroll
        for (int s = 0; s < 8; s++) {
            int li = tid + s * 256;
            int r = li >> 4, kk = li & 15;
            As[kk][r] = x[(size_t)(bm + r) * Dd + k0 + kk] * w[k0 + kk];
            Bs[kk][r] = x[(size_t)(bn + r) * Dd + k0 + kk];
        }
        __syncthreads();
#pragma unroll
        for (int kk = 0; kk < 16; kk++) {
            float a[8], bb[8];
#pragma unroll
            for (int i = 0; i < 8; i++) a[i] = As[kk][ty * 8 + i];
#pragma unroll
            for (int j = 0; j < 8; j++) bb[j] = Bs[kk][tx * 8 + j];
#pragma unroll
            for (int i = 0; i < 8; i++)
#pragma unroll
                for (int j = 0; j < 8; j++) acc[i][j] = fmaf(a[i], bb[j], acc[i][j]);
        }
        __syncthreads();
    }
    float bv = bptr[0];
#pragma unroll
    for (int i = 0; i < 8; i++) {
        int row = bm + ty * 8 + i;
        float qi = g_q[row] + bv;
#pragma unroll
        for (int j = 0; j < 8; j += 4) {
            int col = bn + tx * 8 + j;
            float4 o;
            o.x = sigmoidf_(qi + g_q[col + 0] - 2.f * acc[i][j + 0]);
            o.y = sigmoidf_(qi + g_q[col + 1] - 2.f * acc[i][j + 1]);
            o.z = sigmoidf_(qi + g_q[col + 2] - 2.f * acc[i][j + 2]);
            o.w = sigmoidf_(qi + g_q[col + 3] - 2.f * acc[i][j + 3]);
            *reinterpret_cast<float4*>(&G[(size_t)row * Nn + col]) = o;
        }
    }
}

// ---------------- persistent Lanczos: 4 barriers/iter, shared-staged w --------
__global__ void __launch_bounds__(NT) k_lanczos(const float* __restrict__ G) {
    const int tid = threadIdx.x;
    const int bid = blockIdx.x;
    const int gid = bid * NT + tid;
    const int gw = gid >> 5, lane = gid & 31;
    const int wib = tid >> 5;              // warp in block (0..15)
    const int stripe = gid >> 11;          // 0..36
    const int selem = gid & (Nn - 1);
    const float c0 = rsqrtf((float)Nn);

    __shared__ float s_wu16[16], s_sum16[16];
    __shared__ float s_w[Nn];              // staged w (full vector, 8KB)
    float4* s_w4 = reinterpret_cast<float4*>(s_w);

    // ---- init: V0 = ones*c0, zero acc, v1 = hash - mean; fold rowsum -> deg
    float r = 0.f;
    if (gid < Nn) {
        unsigned u = (unsigned)(gid + 1) * 2654435761u;
        u ^= u >> 16; u *= 2246822519u; u ^= u >> 13; u *= 3266489917u; u ^= u >> 16;
        r = (float)(u & 0xFFFFFFu) * (1.f / 16777216.f) - 0.5f;
        g_V[gid] = c0;
        g_acc[gid] = 0.f;
    }
    if (gid == 0) g_mean = 0.f;
    if (gw < Nn) {      // degree: one warp per row
        const float4* Gr = reinterpret_cast<const float4*>(G + (size_t)gw * Nn);
        float acc = 0.f;
#pragma unroll 4
        for (int t = lane; t < Nn / 4; t += 32) {
            float4 a = Gr[t];
            acc += a.x + a.y + a.z + a.w;
        }
        acc = warpReduceSumF(acc);
        if (lane == 0) g_deg[gw] = acc;
    }
    gbar();
    if (gw < Nn / 32) {
        float s = warpReduceSumF(r);
        if (lane == 0) atomicAdd(&g_mean, s);
    }
    gbar();
    if (gid < Nn) g_w[gid] = r - g_mean * (1.f / (float)Nn);
    gbar();

    for (int j = 1; j <= M_LZ; j++) {
        // ==== Phase A: stage w; beta2 partials; dots1 halves; matvec + partials
        s_w4[tid] = reinterpret_cast<const float4*>(g_w)[tid];   // 512 x float4 = 2048
        __syncthreads();
        if (gid < Nn) {
            float wv = s_w[gid];
            float p = warpReduceSumF(wv * wv);
            if (lane == 0) g_b2part[gw] = p;
        }
        {
            float lwu = 0.f, lsum = 0.f;
            const int nDotWarp = 2 * (j - 1);
            if (gw < nDotWarp) {
                int i = 1 + (gw >> 1);
                int base = (gw & 1) * (Nn / 8);   // float4 index offset
                const float4* lv = reinterpret_cast<const float4*>(g_LV + (size_t)i * Nn) + base;
                const float4* w4 = s_w4 + base;
                float acc = 0.f;
#pragma unroll 4
                for (int t = lane; t < Nn / 8; t += 32) {
                    float4 a = lv[t], bq = w4[t];
                    acc += a.x * bq.x + a.y * bq.y + a.z * bq.z + a.w * bq.w;
                }
                acc = warpReduceSumF(acc);
                if (lane == 0) { if (gw & 1) g_c1b[i] = acc; else g_c1a[i] = acc; }
            } else {
                int row = gw - nDotWarp;
                if (row < Nn) {
                    const float4* Gr = reinterpret_cast<const float4*>(G + (size_t)row * Nn);
                    float acc = 0.f;
#pragma unroll 4
                    for (int t = lane; t < Nn / 4; t += 32) {
                        float4 a = Gr[t], bq = s_w4[t];
                        acc += a.x * bq.x + a.y * bq.y + a.z * bq.z + a.w * bq.w;
                    }
                    acc = warpReduceSumF(acc);
                    if (lane == 0) {
                        float ub = g_deg[row] * s_w[row] - acc;
                        g_ub[row] = ub;
                        lwu = s_w[row] * ub;
                        lsum = ub;
                    }
                }
            }
            if (lane == 0) { s_wu16[wib] = lwu; s_sum16[wib] = lsum; }
        }
        __syncthreads();
        if (tid == 0) {
            float a0 = 0.f, a1 = 0.f;
#pragma unroll
            for (int k = 0; k < 16; k++) { a0 += s_wu16[k]; a1 += s_sum16[k]; }
            g_swupart[bid] = a0;
            g_ssumpart[bid] = a1;
        }
        gbar();

        // ==== Phase B: striped sub1 into acc; stripe0 commits V[j], LV[j]
        if (stripe < 32) {
            float b2l = g_b2part[lane] + g_b2part[lane + 32];
            b2l = warpReduceSumF(b2l);
            float b2 = __shfl_sync(0xffffffffu, b2l, 0);
            float invb = rsqrtf(fmaxf(b2, 1e-30f));
            int t = selem;
            float part = 0.f;
#pragma unroll 4
            for (int i = 1 + stripe; i < j; i += 32)
                part = fmaf((g_c1a[i] + g_c1b[i]) * invb, g_V[(size_t)i * Nn + t], part);
            if (stripe == 0) {
                float swl = 0.f, ssl = 0.f;
                for (int k = lane; k < NB; k += 32) { swl += g_swupart[k]; ssl += g_ssumpart[k]; }
                swl = warpReduceSumF(swl);
                ssl = warpReduceSumF(ssl);
                float swu = __shfl_sync(0xffffffffu, swl, 0);
                float ssum = __shfl_sync(0xffffffffu, ssl, 0);
                float c1j = swu * invb * invb;
                float a0 = c0 * c0 * ssum * invb;
                float wv = g_w[t];
                float vj = wv * invb;
                float uv = g_ub[t] * invb;
                g_V[(size_t)j * Nn + t] = vj;
                g_LV[(size_t)j * Nn + t] = uv;
                part += fmaf(c1j, vj, a0);
                if (gid == 0) { g_beta2[j] = b2; g_c1j = c1j; }
            }
            if (part != 0.f) atomicAdd(&g_acc[t], part);
        }
        gbar();

        // ==== Phase C: dots2 split halves vs (LV[j]-acc); next warps seed w=u
        {
            const int nd = 2 * (j + 1);
            if (gw < nd) {
                int i = gw >> 1;
                int base = (gw & 1) * (Nn / 8);
                const float4* lvj = reinterpret_cast<const float4*>(g_LV + (size_t)j * Nn) + base;
                const float4* ac4 = reinterpret_cast<const float4*>(g_acc) + base;
                const float4* vi = reinterpret_cast<const float4*>(g_V + (size_t)i * Nn) + base;
                float acc = 0.f;
#pragma unroll 4
                for (int t = lane; t < Nn / 8; t += 32) {
                    float4 a = vi[t], u0 = lvj[t], a4 = ac4[t];
                    acc += a.x * (u0.x - a4.x) + a.y * (u0.y - a4.y)
                         + a.z * (u0.z - a4.z) + a.w * (u0.w - a4.w);
                }
                acc = warpReduceSumF(acc);
                if (lane == 0) { if (gw & 1) g_c2b[i] = acc; else g_c2a[i] = acc; }
            } else if (gw < nd + 64) {
                int t = (gw - nd) * 32 + lane;
                g_w[t] = g_LV[(size_t)j * Nn + t] - g_acc[t];
            }
        }
        gbar();

        // ==== Phase D: striped sub2 into w; stripe32 zeroes acc; alpha
        if (stripe < 32) {
            int t = selem;
            float part = 0.f;
#pragma unroll 4
            for (int i = stripe; i <= j; i += 32)
                part = fmaf(g_c2a[i] + g_c2b[i], g_V[(size_t)i * Nn + t], part);
            if (part != 0.f) atomicAdd(&g_w[t], -part);
        } else if (stripe == 32) {
            g_acc[selem] = 0.f;
        }
        if (gid == 0) g_alpha[j] = g_c1j + g_c2a[j] + g_c2b[j];
        gbar();
    }
}

// ---------------- smallest eigenpair of T (m tridiagonal), one warp, fp32 -----
__global__ void k_tridiag() {
    __shared__ float aa[M_LZ], bb2[M_LZ], bbs[M_LZ];
    __shared__ float dw[M_LZ], ew[M_LZ], fw[M_LZ], yv[M_LZ], rv[M_LZ];
    __shared__ float sx[32];
    __shared__ int scnt[32];
    __shared__ float slo, shi;
    int lane = threadIdx.x;
    for (int i = lane; i < M_LZ; i += 32) {
        aa[i] = g_alpha[i + 1];
        float b2 = (i < M_LZ - 1) ? g_beta2[i + 2] : 0.f;
        bb2[i] = b2;
        bbs[i] = sqrtf(b2);
    }
    __syncwarp();
    if (lane == 0) {
        float lo = 3.4e38f, hi = -3.4e38f;
        for (int i = 0; i < M_LZ; i++) {
            float bl = (i > 0) ? bbs[i - 1] : 0.f;
            float br = (i < M_LZ - 1) ? bbs[i] : 0.f;
            lo = fminf(lo, aa[i] - bl - br);
            hi = fmaxf(hi, aa[i] + bl + br);
        }
        slo = lo - 1.f; shi = hi + 1.f;
    }
    __syncwarp();
    // 32-way bisection for lambda_min(T); fp32 floor ~eps*||T||
    for (int round = 0; round < 8; round++) {
        float lo = slo, hi = shi;
        float x = lo + (hi - lo) * (float)(lane + 1) * (1.f / 33.f);
        float d = aa[0] - x;
        int cnt = (d < 0.f);
        for (int i = 1; i < M_LZ; i++) {
            if (fabsf(d) < 1e-20f) d = (d < 0.f ? -1e-20f : 1e-20f);
            d = aa[i] - x - bb2[i - 1] / d;
            cnt += (d < 0.f);
        }
        sx[lane] = x; scnt[lane] = cnt;
        __syncwarp();
        if (lane == 0) {
            float nlo = lo, nhi = hi;
            int k = 0;
            while (k < 32 && scnt[k] < 1) k++;
            if (k < 32) { nhi = sx[k]; if (k > 0) nlo = sx[k - 1]; }
            else        { nlo = sx[31]; }
            slo = nlo; shi = nhi;
        }
        __syncwarp();
    }
    float th = 0.5f * (slo + shi);
    if (lane == 0) {
        // inverse iteration with partial-pivot tridiagonal solve, 3 sweeps, fp32
        for (int i = 0; i < M_LZ; i++) rv[i] = 1.f;
        for (int it = 0; it < 3; it++) {
            for (int i = 0; i < M_LZ; i++) {
                dw[i] = aa[i] - th;
                ew[i] = (i < M_LZ - 1) ? bbs[i] : 0.f;
                fw[i] = 0.f;
                yv[i] = rv[i];
            }
            for (int i = 0; i < M_LZ - 1; i++) {
                float s = bbs[i];
                if (fabsf(s) > fabsf(dw[i])) {
                    float od = dw[i], oe = ew[i], of = fw[i];
                    dw[i] = s;       ew[i] = dw[i + 1]; fw[i] = ew[i + 1];
                    s = od;          dw[i + 1] = oe;    ew[i + 1] = of;
                    float ry = yv[i]; yv[i] = yv[i + 1]; yv[i + 1] = ry;
                }
                float p = dw[i];
                if (fabsf(p) < 1e-20f) { p = (p < 0.f ? -1e-20f : 1e-20f); dw[i] = p; }
                float m = s / p;
                dw[i + 1] -= m * ew[i];
                ew[i + 1] -= m * fw[i];
                yv[i + 1] -= m * yv[i];
            }
            for (int i = M_LZ - 1; i >= 0; i--) {
                float v = yv[i];
                if (i + 1 < M_LZ) v -= ew[i] * yv[i + 1];
                if (i + 2 < M_LZ) v -= fw[i] * yv[i + 2];
                float p = dw[i];
                if (fabsf(p) < 1e-20f) p = (p < 0.f ? -1e-20f : 1e-20f);
                yv[i] = v / p;
            }
            float n2 = 0.f;
            for (int i = 0; i < M_LZ; i++) n2 += yv[i] * yv[i];
            float inv = rsqrtf(fmaxf(n2, 1e-30f));
            for (int i = 0; i < M_LZ; i++) rv[i] = yv[i] * inv;
        }
        for (int i = 0; i < M_LZ; i++) g_y[i] = rv[i];
    }
}

// ---------------- fv = sum_r y_{r-1} V[r] -------------------------------------
__global__ void k_assemble() {
    int t = blockIdx.x * 256 + threadIdx.x;
    float acc = 0.f;
    for (int rr = 1; rr <= M_LZ; rr++)
        acc = fmaf(g_y[rr - 1], g_V[(size_t)rr * Nn + t], acc);
    g_fv[t] = acc;
}

// ---------------- z = L * fv (fp32) -------------------------------------------
__global__ void k_rq(const float* __restrict__ G) {
    __shared__ float sh[8];
    int i = blockIdx.x, tid = threadIdx.x;
    const float* row = G + (size_t)i * Nn;
    float acc = 0.f;
    for (int t = tid; t < Nn; t += 256) acc = fmaf(row[t], g_fv[t], acc);
    acc = blockReduceSumF(acc, sh);
    if (tid == 0) g_z[i] = g_deg[i] * g_fv[i] - acc;
}

// ---------------- value = fv.z / fv.fv; normalize + sign + write --------------
__global__ void k_final(float* __restrict__ out) {
    __shared__ double sh[32];
    __shared__ float sabs[32];
    __shared__ int sidx[32];
    __shared__ double ssign;
    int tid = threadIdx.x;
    double a = (double)g_fv[tid], b = (double)g_fv[tid + 1024];
    double num = blockReduceSumD(a * (double)g_z[tid] + b * (double)g_z[tid + 1024], sh);
    double den = blockReduceSumD(a * a + b * b, sh);
    float bav; int bix;
    float fa = (float)fabs(a), fb = (float)fabs(b);
    if (fa >= fb) { bav = fa; bix = tid; }
    else          { bav = fb; bix = tid + 1024; }
#pragma unroll
    for (int o = 16; o; o >>= 1) {
        float ov = __shfl_down_sync(0xffffffffu, bav, o);
        int   oi = __shfl_down_sync(0xffffffffu, bix, o);
        if (ov > bav || (ov == bav && oi < bix)) { bav = ov; bix = oi; }
    }
    int lane = tid & 31, wid = tid >> 5;
    if (lane == 0) { sabs[wid] = bav; sidx[wid] = bix; }
    __syncthreads();
    if (tid == 0) {
        float bv = sabs[0]; int bi = sidx[0];
        for (int i = 1; i < 32; i++)
            if (sabs[i] > bv || (sabs[i] == bv && sidx[i] < bi)) { bv = sabs[i]; bi = sidx[i]; }
        ssign = (g_fv[bi] >= 0.f ? 1.0 : -1.0) * SIGN_CONV;
        out[(size_t)Nn * Nn] = (float)(num / fmax(den, 1e-300));
    }
    __syncthreads();
    double sc = ssign / sqrt(fmax(den, 1e-300));
    size_t base = (size_t)Nn * Nn + 1;
    out[base + tid]        = (float)(a * sc);
    out[base + tid + 1024] = (float)(b * sc);
}

// ---------------- launcher ----------------------------------------------------
extern "C" void kernel_launch(void* const* d_in, const int* in_sizes, int n_in,
                              void* d_out, int out_size) {
    const float* x = (const float*)d_in[0];
    const float* w = (const float*)d_in[1];
    const float* b = (const float*)d_in[2];
    float* out = (float*)d_out;
    float* G = out;   // grouping matrix lives at the front of d_out

    k_q<<<Nn, 128>>>(x, w);
    k_gemm<<<dim3(Nn / 128, Nn / 128), 256>>>(x, w, b, G);
    k_lanczos<<<NB, NT>>>(G);
    k_tridiag<<<1, 32>>>();
    k_assemble<<<Nn / 256, 256>>>();
    k_rq<<<Nn, 256>>>(G);
    k_final<<<1, 1024>>>(out);
}

// round 15
// speedup vs baseline: 3.1864x; 1.2884x over previous
#include <cuda_runtime.h>
#include <cuda_bf16.h>
#include <math.h>

#define Nn 2048
#define Dd 512
#define M_LZ 128
#define NB 148              // persistent blocks (1 CTA/SM)
#define NT 512
#define NWARP ((NB * NT) / 32)   // 2368 global warps
#define ELD 132             // eps matrix row stride
#ifndef SIGN_CONV
#define SIGN_CONV (-1.0)
#endif

// ---------------- device scratch (static; no runtime allocation) -------------
__device__ float g_q[Nn];
__device__ float g_deg[Nn];
__device__ __align__(16) float g_V[(M_LZ + 1) * Nn];   // row 0 = ones/sqrt(N)
__device__ __align__(16) float g_LV[(M_LZ + 1) * Nn];  // rows 1..M: L * v_i
__device__ __align__(16) float g_wbuf[2 * Nn];         // ping-pong raw candidates
__device__ __align__(16) float g_ub[Nn];               // ubar = L * w_raw
__device__ float g_c1[M_LZ + 2];         // pass-1 raw dots (LV_i . w_raw)
__device__ float g_gj[M_LZ + 2];         // gram raw dots (w_raw . v_k)
__device__ float g_eps[(M_LZ + 2) * ELD]; // Gram-error matrix
__device__ float g_alpha[M_LZ + 2];      // T diagonal (1-based)
__device__ float g_beta2[M_LZ + 2];      // ||w entering iter j||^2
__device__ float g_b2part[64];           // per-warp ||w||^2 partials
__device__ float g_wspart[64];           // per-warp sum(w) partials
__device__ float g_swupart[NB];          // per-block w.ubar partials
__device__ float g_ssumpart[NB];         // per-block sum(ubar) partials
__device__ float g_mean;
__device__ float g_y[M_LZ];              // tridiagonal eigenvector (fp32)
__device__ __align__(16) float g_fv[Nn];
__device__ __align__(16) float g_z[Nn];
// grid barrier state
__device__ unsigned g_cnt8[8 * 32];      // 8 group counters, 128B apart
__device__ unsigned g_root;
__device__ volatile unsigned g_gen;

// ---------------- reduction helpers ------------------------------------------
__device__ __forceinline__ float warpReduceSumF(float v) {
#pragma unroll
    for (int o = 16; o; o >>= 1) v += __shfl_down_sync(0xffffffffu, v, o);
    return v;
}
__device__ __forceinline__ double warpReduceSumD(double v) {
#pragma unroll
    for (int o = 16; o; o >>= 1) v += __shfl_down_sync(0xffffffffu, v, o);
    return v;
}
__device__ __forceinline__ float blockReduceSumF(float v, float* sh) {
    int lane = threadIdx.x & 31, wid = threadIdx.x >> 5;
    v = warpReduceSumF(v);
    __syncthreads();
    if (lane == 0) sh[wid] = v;
    __syncthreads();
    if (wid == 0) {
        int nw = (blockDim.x + 31) >> 5;
        float s = (lane < nw) ? sh[lane] : 0.f;
        s = warpReduceSumF(s);
        if (lane == 0) sh[0] = s;
    }
    __syncthreads();
    return sh[0];
}
__device__ __forceinline__ double blockReduceSumD(double v, double* sh) {
    int lane = threadIdx.x & 31, wid = threadIdx.x >> 5;
    v = warpReduceSumD(v);
    __syncthreads();
    if (lane == 0) sh[wid] = v;
    __syncthreads();
    if (wid == 0) {
        int nw = (blockDim.x + 31) >> 5;
        double s = (lane < nw) ? sh[lane] : 0.0;
        s = warpReduceSumD(s);
        if (lane == 0) sh[0] = s;
    }
    __syncthreads();
    return sh[0];
}

__device__ __forceinline__ float sigmoidf_(float s) {
    if (s >= 0.f) { float ez = __expf(-s); return 1.f / (1.f + ez); }
    float ez = __expf(s); return ez / (1.f + ez);
}

// ---------------- acq_rel grid barrier (two-level tree) -----------------------
__device__ __forceinline__ unsigned atom_add_acqrel(unsigned* p, unsigned v) {
    unsigned old;
    asm volatile("atom.acq_rel.gpu.global.add.u32 %0, [%1], %2;"
                 : "=r"(old) : "l"(p), "r"(v) : "memory");
    return old;
}
__device__ __forceinline__ void st_release_u32(volatile unsigned* p, unsigned v) {
    asm volatile("st.release.gpu.global.u32 [%0], %1;" :: "l"(p), "r"(v) : "memory");
}
__device__ __forceinline__ unsigned ld_acquire_u32(volatile unsigned* p) {
    unsigned v;
    asm volatile("ld.acquire.gpu.global.u32 %0, [%1];" : "=r"(v) : "l"(p) : "memory");
    return v;
}
__device__ __forceinline__ void gbar() {
    __syncthreads();
    if (threadIdx.x == 0) {
        unsigned gen = *(volatile unsigned*)&g_gen;
        int grp = blockIdx.x & 7;
        unsigned gsz = (unsigned)(NB >> 3) + ((unsigned)grp < (unsigned)(NB & 7) ? 1u : 0u);
        bool rel = false;
        if (atom_add_acqrel(&g_cnt8[grp * 32], 1u) == gsz - 1u) {
            g_cnt8[grp * 32] = 0;
            if (atom_add_acqrel(&g_root, 1u) == 7u) {
                g_root = 0;
                st_release_u32(&g_gen, gen + 1);
                rel = true;
            }
        }
        if (!rel) {
            while (ld_acquire_u32(&g_gen) == gen) __nanosleep(16);
        }
    }
    __syncthreads();
}

// ---------------- q_i = sum_k w_k x_ik^2 -------------------------------------
__global__ void k_q(const float* __restrict__ x, const float* __restrict__ w) {
    __shared__ float sh[4];
    int i = blockIdx.x, tid = threadIdx.x;
    float acc = 0.f;
    for (int k = tid; k < Dd; k += 128) {
        float xv = x[(size_t)i * Dd + k];
        acc = fmaf(w[k] * xv, xv, acc);
    }
    acc = blockReduceSumF(acc, sh);
    if (tid == 0) g_q[i] = acc;
}

// ---------------- G = sigmoid(q_i + q_j - 2*X diag(w) X^T + b) ---------------
__global__ void k_gemm(const float* __restrict__ x, const float* __restrict__ w,
                       const float* __restrict__ bptr, float* __restrict__ G) {
    __shared__ float As[16][132];
    __shared__ float Bs[16][132];
    int bm = blockIdx.y * 128, bn = blockIdx.x * 128;
    int tid = threadIdx.x;
    int tx = tid & 15, ty = tid >> 4;
    float acc[8][8];
#pragma unroll
    for (int i = 0; i < 8; i++)
#pragma unroll
        for (int j = 0; j < 8; j++) acc[i][j] = 0.f;

    for (int k0 = 0; k0 < Dd; k0 += 16) {
#pragma unroll
        for (int s = 0; s < 8; s++) {
            int li = tid + s * 256;
            int r = li >> 4, kk = li & 15;
            As[kk][r] = x[(size_t)(bm + r) * Dd + k0 + kk] * w[k0 + kk];
            Bs[kk][r] = x[(size_t)(bn + r) * Dd + k0 + kk];
        }
        __syncthreads();
#pragma unroll
        for (int kk = 0; kk < 16; kk++) {
            float a[8], bb[8];
#pragma unroll
            for (int i = 0; i < 8; i++) a[i] = As[kk][ty * 8 + i];
#pragma unroll
            for (int j = 0; j < 8; j++) bb[j] = Bs[kk][tx * 8 + j];
#pragma unroll
            for (int i = 0; i < 8; i++)
#pragma unroll
                for (int j = 0; j < 8; j++) acc[i][j] = fmaf(a[i], bb[j], acc[i][j]);
        }
        __syncthreads();
    }
    float bv = bptr[0];
#pragma unroll
    for (int i = 0; i < 8; i++) {
        int row = bm + ty * 8 + i;
        float qi = g_q[row] + bv;
#pragma unroll
        for (int j = 0; j < 8; j += 4) {
            int col = bn + tx * 8 + j;
            float4 o;
            o.x = sigmoidf_(qi + g_q[col + 0] - 2.f * acc[i][j + 0]);
            o.y = sigmoidf_(qi + g_q[col + 1] - 2.f * acc[i][j + 1]);
            o.z = sigmoidf_(qi + g_q[col + 2] - 2.f * acc[i][j + 2]);
            o.w = sigmoidf_(qi + g_q[col + 3] - 2.f * acc[i][j + 3]);
            *reinterpret_cast<float4*>(&G[(size_t)row * Nn + col]) = o;
        }
    }
}

// ---------------- persistent Lanczos: 2 barriers/iter (analytic CGS2) ---------
__global__ void __launch_bounds__(NT) k_lanczos(const float* __restrict__ G) {
    const int tid = threadIdx.x;
    const int bid = blockIdx.x;
    const int gid = bid * NT + tid;
    const int gw = gid >> 5, lane = gid & 31;
    const int wib = tid >> 5;              // warp in block (0..15)
    const int stripe = gid >> 11;          // 0..36
    const int selem = gid & (Nn - 1);
    const float c0 = rsqrtf((float)Nn);

    __shared__ alignas(16) float s_w[Nn];  // staged w_raw (8KB) — float4-accessed
    __shared__ float s_wu16[16], s_sum16[16];
    __shared__ float s_scal[3];            // swu, ssum, wsum totals
    __shared__ float s_c1n[M_LZ + 2];
    __shared__ float s_epsj[M_LZ + 2];
    __shared__ float s_coef[M_LZ + 2];
    float4* s_w4 = reinterpret_cast<float4*>(s_w);

    // ---- init: V0 = ones*c0, eps00 = 0, deg = rowsum, v1 = hash - mean -------
    float r = 0.f;
    if (gid < Nn) {
        unsigned u = (unsigned)(gid + 1) * 2654435761u;
        u ^= u >> 16; u *= 2246822519u; u ^= u >> 13; u *= 3266489917u; u ^= u >> 16;
        r = (float)(u & 0xFFFFFFu) * (1.f / 16777216.f) - 0.5f;
        g_V[gid] = c0;
    }
    if (gid == 0) { g_mean = 0.f; g_eps[0] = 0.f; }
    if (gw < Nn) {      // degree: one warp per row
        const float4* Gr = reinterpret_cast<const float4*>(G + (size_t)gw * Nn);
        float acc = 0.f;
#pragma unroll 4
        for (int t = lane; t < Nn / 4; t += 32) {
            float4 a = Gr[t];
            acc += a.x + a.y + a.z + a.w;
        }
        acc = warpReduceSumF(acc);
        if (lane == 0) g_deg[gw] = acc;
    }
    gbar();
    if (gw < Nn / 32) {
        float s = warpReduceSumF(r);
        if (lane == 0) atomicAdd(&g_mean, s);
    }
    gbar();
    if (gid < Nn) g_wbuf[Nn + gid] = r - g_mean * (1.f / (float)Nn);  // W[1]
    gbar();

    for (int j = 1; j <= M_LZ; j++) {
        const float* Wcur = g_wbuf + (size_t)(j & 1) * Nn;
        float* Wnxt = g_wbuf + (size_t)((j + 1) & 1) * Nn;

        // ==== Phase A: stage w; partials; clear Wnxt; dots1; gram; matvec ====
        s_w4[tid] = reinterpret_cast<const float4*>(Wcur)[tid];
        __syncthreads();
        if (gid < Nn) {
            float wv = s_w[gid];
            float p = warpReduceSumF(wv * wv);
            float q = warpReduceSumF(wv);
            if (lane == 0) { g_b2part[gw] = p; g_wspart[gw] = q; }
            Wnxt[gid] = 0.f;
        }
        {
            float lwu = 0.f, lsum = 0.f;
            const int nd = j - 1;
            if (gw < nd) {
                // dots1: c1[i] = LV[i] . w_raw
                int i = 1 + gw;
                const float4* lv = reinterpret_cast<const float4*>(g_LV + (size_t)i * Nn);
                float acc = 0.f;
#pragma unroll 4
                for (int t = lane; t < Nn / 4; t += 32) {
                    float4 a = lv[t], bq = s_w4[t];
                    acc += a.x * bq.x + a.y * bq.y + a.z * bq.z + a.w * bq.w;
                }
                acc = warpReduceSumF(acc);
                if (lane == 0) g_c1[i] = acc;
            } else if (gw < 2 * nd) {
                // gram: gj[k] = w_raw . v_k
                int k = 1 + (gw - nd);
                const float4* vk = reinterpret_cast<const float4*>(g_V + (size_t)k * Nn);
                float acc = 0.f;
#pragma unroll 4
                for (int t = lane; t < Nn / 4; t += 32) {
                    float4 a = vk[t], bq = s_w4[t];
                    acc += a.x * bq.x + a.y * bq.y + a.z * bq.z + a.w * bq.w;
                }
                acc = warpReduceSumF(acc);
                if (lane == 0) g_gj[k] = acc;
            } else {
                int row = gw - 2 * nd;
                if (row < Nn) {
                    const float4* Gr = reinterpret_cast<const float4*>(G + (size_t)row * Nn);
                    float acc = 0.f;
#pragma unroll 4
                    for (int t = lane; t < Nn / 4; t += 32) {
                        float4 a = Gr[t], bq = s_w4[t];
                        acc += a.x * bq.x + a.y * bq.y + a.z * bq.z + a.w * bq.w;
                    }
                    acc = warpReduceSumF(acc);
                    if (lane == 0) {
                        float ub = g_deg[row] * s_w[row] - acc;
                        g_ub[row] = ub;
                        lwu = s_w[row] * ub;
                        lsum = ub;
                    }
                }
            }
            if (lane == 0) { s_wu16[wib] = lwu; s_sum16[wib] = lsum; }
        }
        __syncthreads();
        if (tid == 0) {
            float a0 = 0.f, a1 = 0.f;
#pragma unroll
            for (int k = 0; k < 16; k++) { a0 += s_wu16[k]; a1 += s_sum16[k]; }
            g_swupart[bid] = a0;
            g_ssumpart[bid] = a1;
        }
        gbar();

        // ==== Phase B: scalars; c1n/epsj; c2 = -eps*c1n; combined subtraction =
        float b2l = g_b2part[lane] + g_b2part[lane + 32];
        b2l = warpReduceSumF(b2l);
        float b2 = __shfl_sync(0xffffffffu, b2l, 0);
        float invb = rsqrtf(fmaxf(b2, 1e-30f));
        if (wib == 0) {
            float swl = 0.f, ssl = 0.f;
            for (int k = lane; k < NB; k += 32) { swl += g_swupart[k]; ssl += g_ssumpart[k]; }
            float wsl = g_wspart[lane] + g_wspart[lane + 32];
            swl = warpReduceSumF(swl);
            ssl = warpReduceSumF(ssl);
            wsl = warpReduceSumF(wsl);
            if (lane == 0) { s_scal[0] = swl; s_scal[1] = ssl; s_scal[2] = wsl; }
        }
        __syncthreads();
        if (tid <= j) {
            int i = tid;
            float c1n, ej;
            if (i == 0)      { c1n = c0 * s_scal[1] * invb; ej = c0 * s_scal[2] * invb; }
            else if (i == j) { c1n = s_scal[0] * invb * invb; ej = b2 * invb * invb - 1.f; }
            else             { c1n = g_c1[i] * invb; ej = g_gj[i] * invb; }
            s_c1n[i] = c1n;
            s_epsj[i] = ej;
        }
        __syncthreads();
        for (int i = wib; i <= j; i += 16) {
            float acc = 0.f;
            if (i == j) {
                for (int k = lane; k <= j; k += 32) acc += s_c1n[k] * s_epsj[k];
            } else {
                const float* er = g_eps + (size_t)i * ELD;
                for (int k = lane; k <= j; k += 32) {
                    float e = (k == j) ? s_epsj[i] : er[k];
                    acc += s_c1n[k] * e;
                }
            }
            acc = warpReduceSumF(acc);
            if (lane == 0) s_coef[i] = s_c1n[i] - acc;   // c1n_i + c2_i
        }
        __syncthreads();
        if (bid == 0 && tid <= j) {                      // commit eps row/col j
            g_eps[(size_t)j * ELD + tid] = s_epsj[tid];
            g_eps[(size_t)tid * ELD + j] = s_epsj[tid];
        }
        if (stripe < 32 && (stripe == 0 || stripe < j)) {
            int t = selem;
            float part = 0.f;
#pragma unroll 4
            for (int i = stripe; i < j; i += 32)
                part = fmaf(s_coef[i], g_V[(size_t)i * Nn + t], part);
            if (stripe == 0) {
                float wv = s_w[t];
                float vj = wv * invb;
                float uv = g_ub[t] * invb;
                g_V[(size_t)j * Nn + t] = vj;
                g_LV[(size_t)j * Nn + t] = uv;
                part = fmaf(s_coef[j], vj, part) - uv;   // include i=j term; seed u
            }
            atomicAdd(&Wnxt[t], -part);
        }
        if (gid == 0) { g_beta2[j] = b2; g_alpha[j] = s_coef[j]; }
        gbar();
    }
}

// ---------------- smallest eigenpair of T (m tridiagonal), one warp, fp32 -----
__global__ void k_tridiag() {
    __shared__ float aa[M_LZ], bb2[M_LZ], bbs[M_LZ];
    __shared__ float dw[M_LZ], ew[M_LZ], fw[M_LZ], yv[M_LZ], rv[M_LZ];
    __shared__ float sx[32];
    __shared__ int scnt[32];
    __shared__ float slo, shi;
    int lane = threadIdx.x;
    for (int i = lane; i < M_LZ; i += 32) {
        aa[i] = g_alpha[i + 1];
        float b2 = (i < M_LZ - 1) ? g_beta2[i + 2] : 0.f;
        bb2[i] = b2;
        bbs[i] = sqrtf(b2);
    }
    __syncwarp();
    if (lane == 0) {
        float lo = 3.4e38f, hi = -3.4e38f;
        for (int i = 0; i < M_LZ; i++) {
            float bl = (i > 0) ? bbs[i - 1] : 0.f;
            float br = (i < M_LZ - 1) ? bbs[i] : 0.f;
            lo = fminf(lo, aa[i] - bl - br);
            hi = fmaxf(hi, aa[i] + bl + br);
        }
        slo = lo - 1.f; shi = hi + 1.f;
    }
    __syncwarp();
    for (int round = 0; round < 5; round++) {
        float lo = slo, hi = shi;
        float x = lo + (hi - lo) * (float)(lane + 1) * (1.f / 33.f);
        float d = aa[0] - x;
        int cnt = (d < 0.f);
        for (int i = 1; i < M_LZ; i++) {
            if (fabsf(d) < 1e-20f) d = (d < 0.f ? -1e-20f : 1e-20f);
            d = aa[i] - x - bb2[i - 1] / d;
            cnt += (d < 0.f);
        }
        sx[lane] = x; scnt[lane] = cnt;
        __syncwarp();
        if (lane == 0) {
            float nlo = lo, nhi = hi;
            int k = 0;
            while (k < 32 && scnt[k] < 1) k++;
            if (k < 32) { nhi = sx[k]; if (k > 0) nlo = sx[k - 1]; }
            else        { nlo = sx[31]; }
            slo = nlo; shi = nhi;
        }
        __syncwarp();
    }
    float th = 0.5f * (slo + shi);
    if (lane == 0) {
        for (int i = 0; i < M_LZ; i++) rv[i] = 1.f;
        for (int it = 0; it < 3; it++) {
            for (int i = 0; i < M_LZ; i++) {
                dw[i] = aa[i] - th;
                ew[i] = (i < M_LZ - 1) ? bbs[i] : 0.f;
                fw[i] = 0.f;
                yv[i] = rv[i];
            }
            for (int i = 0; i < M_LZ - 1; i++) {
                float s = bbs[i];
                if (fabsf(s) > fabsf(dw[i])) {
                    float od = dw[i], oe = ew[i], of = fw[i];
                    dw[i] = s;       ew[i] = dw[i + 1]; fw[i] = ew[i + 1];
                    s = od;          dw[i + 1] = oe;    ew[i + 1] = of;
                    float ry = yv[i]; yv[i] = yv[i + 1]; yv[i + 1] = ry;
                }
                float p = dw[i];
                if (fabsf(p) < 1e-20f) { p = (p < 0.f ? -1e-20f : 1e-20f); dw[i] = p; }
                float m = s / p;
                dw[i + 1] -= m * ew[i];
                ew[i + 1] -= m * fw[i];
                yv[i + 1] -= m * yv[i];
            }
            for (int i = M_LZ - 1; i >= 0; i--) {
                float v = yv[i];
                if (i + 1 < M_LZ) v -= ew[i] * yv[i + 1];
                if (i + 2 < M_LZ) v -= fw[i] * yv[i + 2];
                float p = dw[i];
                if (fabsf(p) < 1e-20f) p = (p < 0.f ? -1e-20f : 1e-20f);
                yv[i] = v / p;
            }
            float n2 = 0.f;
            for (int i = 0; i < M_LZ; i++) n2 += yv[i] * yv[i];
            float inv = rsqrtf(fmaxf(n2, 1e-30f));
            for (int i = 0; i < M_LZ; i++) rv[i] = yv[i] * inv;
        }
        for (int i = 0; i < M_LZ; i++) g_y[i] = rv[i];
    }
}

// ---------------- fv = sum_r y_{r-1} V[r] -------------------------------------
__global__ void k_assemble() {
    int t = blockIdx.x * 256 + threadIdx.x;
    float acc = 0.f;
    for (int rr = 1; rr <= M_LZ; rr++)
        acc = fmaf(g_y[rr - 1], g_V[(size_t)rr * Nn + t], acc);
    g_fv[t] = acc;
}

// ---------------- z = L * fv (fp32) -------------------------------------------
__global__ void k_rq(const float* __restrict__ G) {
    __shared__ float sh[8];
    int i = blockIdx.x, tid = threadIdx.x;
    const float* row = G + (size_t)i * Nn;
    float acc = 0.f;
    for (int t = tid; t < Nn; t += 256) acc = fmaf(row[t], g_fv[t], acc);
    acc = blockReduceSumF(acc, sh);
    if (tid == 0) g_z[i] = g_deg[i] * g_fv[i] - acc;
}

// ---------------- value = fv.z / fv.fv; normalize + sign + write --------------
__global__ void k_final(float* __restrict__ out) {
    __shared__ double sh[32];
    __shared__ float sabs[32];
    __shared__ int sidx[32];
    __shared__ double ssign;
    int tid = threadIdx.x;
    double a = (double)g_fv[tid], b = (double)g_fv[tid + 1024];
    double num = blockReduceSumD(a * (double)g_z[tid] + b * (double)g_z[tid + 1024], sh);
    double den = blockReduceSumD(a * a + b * b, sh);
    float bav; int bix;
    float fa = (float)fabs(a), fb = (float)fabs(b);
    if (fa >= fb) { bav = fa; bix = tid; }
    else          { bav = fb; bix = tid + 1024; }
#pragma unroll
    for (int o = 16; o; o >>= 1) {
        float ov = __shfl_down_sync(0xffffffffu, bav, o);
        int   oi = __shfl_down_sync(0xffffffffu, bix, o);
        if (ov > bav || (ov == bav && oi < bix)) { bav = ov; bix = oi; }
    }
    int lane = tid & 31, wid = tid >> 5;
    if (lane == 0) { sabs[wid] = bav; sidx[wid] = bix; }
    __syncthreads();
    if (tid == 0) {
        float bv = sabs[0]; int bi = sidx[0];
        for (int i = 1; i < 32; i++)
            if (sabs[i] > bv || (sabs[i] == bv && sidx[i] < bi)) { bv = sabs[i]; bi = sidx[i]; }
        ssign = (g_fv[bi] >= 0.f ? 1.0 : -1.0) * SIGN_CONV;
        out[(size_t)Nn * Nn] = (float)(num / fmax(den, 1e-300));
    }
    __syncthreads();
    double sc = ssign / sqrt(fmax(den, 1e-300));
    size_t base = (size_t)Nn * Nn + 1;
    out[base + tid]        = (float)(a * sc);
    out[base + tid + 1024] = (float)(b * sc);
}

// ---------------- launcher ----------------------------------------------------
extern "C" void kernel_launch(void* const* d_in, const int* in_sizes, int n_in,
                              void* d_out, int out_size) {
    const float* x = (const float*)d_in[0];
    const float* w = (const float*)d_in[1];
    const float* b = (const float*)d_in[2];
    float* out = (float*)d_out;
    float* G = out;   // grouping matrix lives at the front of d_out

    k_q<<<Nn, 128>>>(x, w);
    k_gemm<<<dim3(Nn / 128, Nn / 128), 256>>>(x, w, b, G);
    k_lanczos<<<NB, NT>>>(G);
    k_tridiag<<<1, 32>>>();
    k_assemble<<<Nn / 256, 256>>>();
    k_rq<<<Nn, 256>>>(G);
    k_final<<<1, 1024>>>(out);
}

// round 16
// speedup vs baseline: 3.3136x; 1.0399x over previous
#include <cuda_runtime.h>
#include <cuda_bf16.h>
#include <math.h>

#define Nn 2048
#define Dd 512
#define M_LZ 128
#define NB 148              // persistent blocks (1 CTA/SM)
#define NT 512
#define NWARP ((NB * NT) / 32)   // 2368 global warps
#define ELD 132             // eps matrix row stride
#ifndef SIGN_CONV
#define SIGN_CONV (-1.0)
#endif

// ---------------- device scratch (static; no runtime allocation) -------------
__device__ float g_q[Nn];
__device__ float g_deg[Nn];
__device__ __align__(16) float g_V[(M_LZ + 1) * Nn];   // row 0 = ones/sqrt(N)
__device__ __align__(16) float g_LV[(M_LZ + 1) * Nn];  // rows 1..M: L * v_i
__device__ __align__(16) float g_wbuf[2 * Nn];         // ping-pong raw candidates
__device__ __align__(16) float g_ub[Nn];               // ubar = L * w_raw
__device__ float g_c1[M_LZ + 2];         // pass-1 raw dots (LV_i . w_raw)
__device__ float g_gj[M_LZ + 2];         // gram raw dots (w_raw . v_k)
__device__ float g_eps[(M_LZ + 2) * ELD]; // Gram-error matrix
__device__ float g_alpha[M_LZ + 2];      // T diagonal (1-based)
__device__ float g_beta2[M_LZ + 2];      // ||w entering iter j||^2
__device__ float g_b2part[64];           // per-warp ||w||^2 partials
__device__ float g_wspart[64];           // per-warp sum(w) partials
__device__ float g_swupart[NB];          // per-block w.ubar partials
__device__ float g_ssumpart[NB];         // per-block sum(ubar) partials
__device__ float g_mean;
__device__ float g_y[M_LZ];              // tridiagonal eigenvector (fp32)
__device__ __align__(16) float g_fv[Nn];
__device__ __align__(16) float g_z[Nn];
// grid barrier state
__device__ unsigned g_cnt8[8 * 32];      // 8 group counters, 128B apart
__device__ unsigned g_root;
__device__ volatile unsigned g_gen;

// ---------------- reduction helpers ------------------------------------------
__device__ __forceinline__ float warpReduceSumF(float v) {
#pragma unroll
    for (int o = 16; o; o >>= 1) v += __shfl_down_sync(0xffffffffu, v, o);
    return v;
}
__device__ __forceinline__ double warpReduceSumD(double v) {
#pragma unroll
    for (int o = 16; o; o >>= 1) v += __shfl_down_sync(0xffffffffu, v, o);
    return v;
}
__device__ __forceinline__ float blockReduceSumF(float v, float* sh) {
    int lane = threadIdx.x & 31, wid = threadIdx.x >> 5;
    v = warpReduceSumF(v);
    __syncthreads();
    if (lane == 0) sh[wid] = v;
    __syncthreads();
    if (wid == 0) {
        int nw = (blockDim.x + 31) >> 5;
        float s = (lane < nw) ? sh[lane] : 0.f;
        s = warpReduceSumF(s);
        if (lane == 0) sh[0] = s;
    }
    __syncthreads();
    return sh[0];
}
__device__ __forceinline__ double blockReduceSumD(double v, double* sh) {
    int lane = threadIdx.x & 31, wid = threadIdx.x >> 5;
    v = warpReduceSumD(v);
    __syncthreads();
    if (lane == 0) sh[wid] = v;
    __syncthreads();
    if (wid == 0) {
        int nw = (blockDim.x + 31) >> 5;
        double s = (lane < nw) ? sh[lane] : 0.0;
        s = warpReduceSumD(s);
        if (lane == 0) sh[0] = s;
    }
    __syncthreads();
    return sh[0];
}

__device__ __forceinline__ float sigmoidf_(float s) {
    if (s >= 0.f) { float ez = __expf(-s); return 1.f / (1.f + ez); }
    float ez = __expf(s); return ez / (1.f + ez);
}

// ---------------- acq_rel grid barrier (two-level tree) -----------------------
__device__ __forceinline__ unsigned atom_add_acqrel(unsigned* p, unsigned v) {
    unsigned old;
    asm volatile("atom.acq_rel.gpu.global.add.u32 %0, [%1], %2;"
                 : "=r"(old) : "l"(p), "r"(v) : "memory");
    return old;
}
__device__ __forceinline__ void st_release_u32(volatile unsigned* p, unsigned v) {
    asm volatile("st.release.gpu.global.u32 [%0], %1;" :: "l"(p), "r"(v) : "memory");
}
__device__ __forceinline__ unsigned ld_acquire_u32(volatile unsigned* p) {
    unsigned v;
    asm volatile("ld.acquire.gpu.global.u32 %0, [%1];" : "=r"(v) : "l"(p) : "memory");
    return v;
}
__device__ __forceinline__ void gbar() {
    __syncthreads();
    if (threadIdx.x == 0) {
        unsigned gen = *(volatile unsigned*)&g_gen;
        int grp = blockIdx.x & 7;
        unsigned gsz = (unsigned)(NB >> 3) + ((unsigned)grp < (unsigned)(NB & 7) ? 1u : 0u);
        bool rel = false;
        if (atom_add_acqrel(&g_cnt8[grp * 32], 1u) == gsz - 1u) {
            g_cnt8[grp * 32] = 0;
            if (atom_add_acqrel(&g_root, 1u) == 7u) {
                g_root = 0;
                st_release_u32(&g_gen, gen + 1);
                rel = true;
            }
        }
        if (!rel) {
            while (ld_acquire_u32(&g_gen) == gen) __nanosleep(16);
        }
    }
    __syncthreads();
}

// ---------------- q_i = sum_k w_k x_ik^2 -------------------------------------
__global__ void k_q(const float* __restrict__ x, const float* __restrict__ w) {
    __shared__ float sh[4];
    int i = blockIdx.x, tid = threadIdx.x;
    float acc = 0.f;
    for (int k = tid; k < Dd; k += 128) {
        float xv = x[(size_t)i * Dd + k];
        acc = fmaf(w[k] * xv, xv, acc);
    }
    acc = blockReduceSumF(acc, sh);
    if (tid == 0) g_q[i] = acc;
}

// ---------------- G = sigmoid(q_i + q_j - 2*X diag(w) X^T + b) ---------------
__global__ void k_gemm(const float* __restrict__ x, const float* __restrict__ w,
                       const float* __restrict__ bptr, float* __restrict__ G) {
    __shared__ float As[16][132];
    __shared__ float Bs[16][132];
    int bm = blockIdx.y * 128, bn = blockIdx.x * 128;
    int tid = threadIdx.x;
    int tx = tid & 15, ty = tid >> 4;
    float acc[8][8];
#pragma unroll
    for (int i = 0; i < 8; i++)
#pragma unroll
        for (int j = 0; j < 8; j++) acc[i][j] = 0.f;

    for (int k0 = 0; k0 < Dd; k0 += 16) {
#pragma unroll
        for (int s = 0; s < 8; s++) {
            int li = tid + s * 256;
            int r = li >> 4, kk = li & 15;
            As[kk][r] = x[(size_t)(bm + r) * Dd + k0 + kk] * w[k0 + kk];
            Bs[kk][r] = x[(size_t)(bn + r) * Dd + k0 + kk];
        }
        __syncthreads();
#pragma unroll
        for (int kk = 0; kk < 16; kk++) {
            float a[8], bb[8];
#pragma unroll
            for (int i = 0; i < 8; i++) a[i] = As[kk][ty * 8 + i];
#pragma unroll
            for (int j = 0; j < 8; j++) bb[j] = Bs[kk][tx * 8 + j];
#pragma unroll
            for (int i = 0; i < 8; i++)
#pragma unroll
                for (int j = 0; j < 8; j++) acc[i][j] = fmaf(a[i], bb[j], acc[i][j]);
        }
        __syncthreads();
    }
    float bv = bptr[0];
#pragma unroll
    for (int i = 0; i < 8; i++) {
        int row = bm + ty * 8 + i;
        float qi = g_q[row] + bv;
#pragma unroll
        for (int j = 0; j < 8; j += 4) {
            int col = bn + tx * 8 + j;
            float4 o;
            o.x = sigmoidf_(qi + g_q[col + 0] - 2.f * acc[i][j + 0]);
            o.y = sigmoidf_(qi + g_q[col + 1] - 2.f * acc[i][j + 1]);
            o.z = sigmoidf_(qi + g_q[col + 2] - 2.f * acc[i][j + 2]);
            o.w = sigmoidf_(qi + g_q[col + 3] - 2.f * acc[i][j + 3]);
            *reinterpret_cast<float4*>(&G[(size_t)row * Nn + col]) = o;
        }
    }
}

// ---------------- persistent Lanczos: 2 barriers/iter (analytic CGS2) ---------
__global__ void __launch_bounds__(NT) k_lanczos(const float* __restrict__ G) {
    const int tid = threadIdx.x;
    const int bid = blockIdx.x;
    const int gid = bid * NT + tid;
    const int gw = gid >> 5, lane = gid & 31;
    const int wib = tid >> 5;              // warp in block (0..15)
    const int stripe = gid >> 11;          // 0..36
    const int selem = gid & (Nn - 1);
    const float c0 = rsqrtf((float)Nn);

    __shared__ alignas(16) float s_w[Nn];  // staged w_raw (8KB) — float4-accessed
    __shared__ float s_wu16[16], s_sum16[16];
    __shared__ float s_scal[3];            // swu, ssum, wsum totals
    __shared__ float s_c1n[M_LZ + 2];
    __shared__ float s_epsj[M_LZ + 2];
    __shared__ float s_coef[M_LZ + 2];
    float4* s_w4 = reinterpret_cast<float4*>(s_w);

    // ---- init: V0 = ones*c0, eps00 = 0, deg = rowsum, v1 = hash - mean -------
    float r = 0.f;
    if (gid < Nn) {
        unsigned u = (unsigned)(gid + 1) * 2654435761u;
        u ^= u >> 16; u *= 2246822519u; u ^= u >> 13; u *= 3266489917u; u ^= u >> 16;
        r = (float)(u & 0xFFFFFFu) * (1.f / 16777216.f) - 0.5f;
        g_V[gid] = c0;
    }
    if (gid == 0) { g_mean = 0.f; g_eps[0] = 0.f; }
    if (gw < Nn) {      // degree: one warp per row
        const float4* Gr = reinterpret_cast<const float4*>(G + (size_t)gw * Nn);
        float acc = 0.f;
#pragma unroll 4
        for (int t = lane; t < Nn / 4; t += 32) {
            float4 a = Gr[t];
            acc += a.x + a.y + a.z + a.w;
        }
        acc = warpReduceSumF(acc);
        if (lane == 0) g_deg[gw] = acc;
    }
    gbar();
    if (gw < Nn / 32) {
        float s = warpReduceSumF(r);
        if (lane == 0) atomicAdd(&g_mean, s);
    }
    gbar();
    if (gid < Nn) g_wbuf[Nn + gid] = r - g_mean * (1.f / (float)Nn);  // W[1]
    gbar();

    for (int j = 1; j <= M_LZ; j++) {
        const float* Wcur = g_wbuf + (size_t)(j & 1) * Nn;
        float* Wnxt = g_wbuf + (size_t)((j + 1) & 1) * Nn;

        // ==== Phase A: stage w; partials; clear Wnxt; dots1; gram; matvec ====
        s_w4[tid] = reinterpret_cast<const float4*>(Wcur)[tid];
        __syncthreads();
        if (gid < Nn) {
            float wv = s_w[gid];
            float p = warpReduceSumF(wv * wv);
            float q = warpReduceSumF(wv);
            if (lane == 0) { g_b2part[gw] = p; g_wspart[gw] = q; }
            Wnxt[gid] = 0.f;
        }
        {
            float lwu = 0.f, lsum = 0.f;
            const int nd = j - 1;
            if (gw < nd) {
                // dots1: c1[i] = LV[i] . w_raw
                int i = 1 + gw;
                const float4* lv = reinterpret_cast<const float4*>(g_LV + (size_t)i * Nn);
                float acc = 0.f;
#pragma unroll 4
                for (int t = lane; t < Nn / 4; t += 32) {
                    float4 a = lv[t], bq = s_w4[t];
                    acc += a.x * bq.x + a.y * bq.y + a.z * bq.z + a.w * bq.w;
                }
                acc = warpReduceSumF(acc);
                if (lane == 0) g_c1[i] = acc;
            } else if (gw < 2 * nd) {
                // gram: gj[k] = w_raw . v_k
                int k = 1 + (gw - nd);
                const float4* vk = reinterpret_cast<const float4*>(g_V + (size_t)k * Nn);
                float acc = 0.f;
#pragma unroll 4
                for (int t = lane; t < Nn / 4; t += 32) {
                    float4 a = vk[t], bq = s_w4[t];
                    acc += a.x * bq.x + a.y * bq.y + a.z * bq.z + a.w * bq.w;
                }
                acc = warpReduceSumF(acc);
                if (lane == 0) g_gj[k] = acc;
            } else {
                int row = gw - 2 * nd;
                if (row < Nn) {
                    const float4* Gr = reinterpret_cast<const float4*>(G + (size_t)row * Nn);
                    float acc = 0.f;
#pragma unroll 4
                    for (int t = lane; t < Nn / 4; t += 32) {
                        float4 a = Gr[t], bq = s_w4[t];
                        acc += a.x * bq.x + a.y * bq.y + a.z * bq.z + a.w * bq.w;
                    }
                    acc = warpReduceSumF(acc);
                    if (lane == 0) {
                        float ub = g_deg[row] * s_w[row] - acc;
                        g_ub[row] = ub;
                        lwu = s_w[row] * ub;
                        lsum = ub;
                    }
                }
            }
            if (lane == 0) { s_wu16[wib] = lwu; s_sum16[wib] = lsum; }
        }
        __syncthreads();
        if (tid == 0) {
            float a0 = 0.f, a1 = 0.f;
#pragma unroll
            for (int k = 0; k < 16; k++) { a0 += s_wu16[k]; a1 += s_sum16[k]; }
            g_swupart[bid] = a0;
            g_ssumpart[bid] = a1;
        }
        gbar();

        // ==== Phase B: scalars; c1n/epsj; c2 = -eps*c1n; combined subtraction =
        float b2l = g_b2part[lane] + g_b2part[lane + 32];
        b2l = warpReduceSumF(b2l);
        float b2 = __shfl_sync(0xffffffffu, b2l, 0);
        float invb = rsqrtf(fmaxf(b2, 1e-30f));
        if (wib == 0) {
            float swl = 0.f, ssl = 0.f;
            for (int k = lane; k < NB; k += 32) { swl += g_swupart[k]; ssl += g_ssumpart[k]; }
            float wsl = g_wspart[lane] + g_wspart[lane + 32];
            swl = warpReduceSumF(swl);
            ssl = warpReduceSumF(ssl);
            wsl = warpReduceSumF(wsl);
            if (lane == 0) { s_scal[0] = swl; s_scal[1] = ssl; s_scal[2] = wsl; }
        }
        __syncthreads();
        if (tid <= j) {
            int i = tid;
            float c1n, ej;
            if (i == 0)      { c1n = c0 * s_scal[1] * invb; ej = c0 * s_scal[2] * invb; }
            else if (i == j) { c1n = s_scal[0] * invb * invb; ej = b2 * invb * invb - 1.f; }
            else             { c1n = g_c1[i] * invb; ej = g_gj[i] * invb; }
            s_c1n[i] = c1n;
            s_epsj[i] = ej;
        }
        __syncthreads();
        for (int i = wib; i <= j; i += 16) {
            float acc = 0.f;
            if (i == j) {
                for (int k = lane; k <= j; k += 32) acc += s_c1n[k] * s_epsj[k];
            } else {
                const float* er = g_eps + (size_t)i * ELD;
                for (int k = lane; k <= j; k += 32) {
                    float e = (k == j) ? s_epsj[i] : er[k];
                    acc += s_c1n[k] * e;
                }
            }
            acc = warpReduceSumF(acc);
            if (lane == 0) s_coef[i] = s_c1n[i] - acc;   // c1n_i + c2_i
        }
        __syncthreads();
        if (bid == 0 && tid <= j) {                      // commit eps row/col j
            g_eps[(size_t)j * ELD + tid] = s_epsj[tid];
            g_eps[(size_t)tid * ELD + j] = s_epsj[tid];
        }
        if (stripe < 32 && (stripe == 0 || stripe < j)) {
            int t = selem;
            float part = 0.f;
#pragma unroll 4
            for (int i = stripe; i < j; i += 32)
                part = fmaf(s_coef[i], g_V[(size_t)i * Nn + t], part);
            if (stripe == 0) {
                float wv = s_w[t];
                float vj = wv * invb;
                float uv = g_ub[t] * invb;
                g_V[(size_t)j * Nn + t] = vj;
                g_LV[(size_t)j * Nn + t] = uv;
                part = fmaf(s_coef[j], vj, part) - uv;   // include i=j term; seed u
            }
            atomicAdd(&Wnxt[t], -part);
        }
        if (gid == 0) { g_beta2[j] = b2; g_alpha[j] = s_coef[j]; }
        gbar();
    }
}

// ---------------- smallest eigenpair of T (m tridiagonal), one warp, fp32 -----
__global__ void k_tridiag() {
    __shared__ float aa[M_LZ], bb2[M_LZ], bbs[M_LZ];
    __shared__ float dw[M_LZ], ew[M_LZ], fw[M_LZ], yv[M_LZ], rv[M_LZ];
    __shared__ float sx[32];
    __shared__ int scnt[32];
    __shared__ float slo, shi;
    int lane = threadIdx.x;
    for (int i = lane; i < M_LZ; i += 32) {
        aa[i] = g_alpha[i + 1];
        float b2 = (i < M_LZ - 1) ? g_beta2[i + 2] : 0.f;
        bb2[i] = b2;
        bbs[i] = sqrtf(b2);
    }
    __syncwarp();
    if (lane == 0) {
        float lo = 3.4e38f, hi = -3.4e38f;
        for (int i = 0; i < M_LZ; i++) {
            float bl = (i > 0) ? bbs[i - 1] : 0.f;
            float br = (i < M_LZ - 1) ? bbs[i] : 0.f;
            lo = fminf(lo, aa[i] - bl - br);
            hi = fmaxf(hi, aa[i] + bl + br);
        }
        slo = lo - 1.f; shi = hi + 1.f;
    }
    __syncwarp();
    for (int round = 0; round < 5; round++) {
        float lo = slo, hi = shi;
        float x = lo + (hi - lo) * (float)(lane + 1) * (1.f / 33.f);
        float d = aa[0] - x;
        int cnt = (d < 0.f);
        for (int i = 1; i < M_LZ; i++) {
            if (fabsf(d) < 1e-20f) d = (d < 0.f ? -1e-20f : 1e-20f);
            d = aa[i] - x - __fdividef(bb2[i - 1], d);
            cnt += (d < 0.f);
        }
        sx[lane] = x; scnt[lane] = cnt;
        __syncwarp();
        if (lane == 0) {
            float nlo = lo, nhi = hi;
            int k = 0;
            while (k < 32 && scnt[k] < 1) k++;
            if (k < 32) { nhi = sx[k]; if (k > 0) nlo = sx[k - 1]; }
            else        { nlo = sx[31]; }
            slo = nlo; shi = nhi;
        }
        __syncwarp();
    }
    float th = 0.5f * (slo + shi);
    if (lane == 0) {
        for (int i = 0; i < M_LZ; i++) rv[i] = 1.f;
        for (int it = 0; it < 2; it++) {
            for (int i = 0; i < M_LZ; i++) {
                dw[i] = aa[i] - th;
                ew[i] = (i < M_LZ - 1) ? bbs[i] : 0.f;
                fw[i] = 0.f;
                yv[i] = rv[i];
            }
            for (int i = 0; i < M_LZ - 1; i++) {
                float s = bbs[i];
                if (fabsf(s) > fabsf(dw[i])) {
                    float od = dw[i], oe = ew[i], of = fw[i];
                    dw[i] = s;       ew[i] = dw[i + 1]; fw[i] = ew[i + 1];
                    s = od;          dw[i + 1] = oe;    ew[i + 1] = of;
                    float ry = yv[i]; yv[i] = yv[i + 1]; yv[i + 1] = ry;
                }
                float p = dw[i];
                if (fabsf(p) < 1e-20f) { p = (p < 0.f ? -1e-20f : 1e-20f); dw[i] = p; }
                float m = __fdividef(s, p);
                dw[i + 1] -= m * ew[i];
                ew[i + 1] -= m * fw[i];
                yv[i + 1] -= m * yv[i];
            }
            for (int i = M_LZ - 1; i >= 0; i--) {
                float v = yv[i];
                if (i + 1 < M_LZ) v -= ew[i] * yv[i + 1];
                if (i + 2 < M_LZ) v -= fw[i] * yv[i + 2];
                float p = dw[i];
                if (fabsf(p) < 1e-20f) p = (p < 0.f ? -1e-20f : 1e-20f);
                yv[i] = __fdividef(v, p);
            }
            float n2 = 0.f;
            for (int i = 0; i < M_LZ; i++) n2 += yv[i] * yv[i];
            float inv = rsqrtf(fmaxf(n2, 1e-30f));
            for (int i = 0; i < M_LZ; i++) rv[i] = yv[i] * inv;
        }
        for (int i = 0; i < M_LZ; i++) g_y[i] = rv[i];
    }
}

// ---------------- fv = sum_r y_{r-1} V[r] -------------------------------------
__global__ void k_assemble() {
    int t = blockIdx.x * 256 + threadIdx.x;
    float acc = 0.f;
    for (int rr = 1; rr <= M_LZ; rr++)
        acc = fmaf(g_y[rr - 1], g_V[(size_t)rr * Nn + t], acc);
    g_fv[t] = acc;
}

// ---------------- z = L * fv (fp32) -------------------------------------------
__global__ void k_rq(const float* __restrict__ G) {
    __shared__ float sh[8];
    int i = blockIdx.x, tid = threadIdx.x;
    const float* row = G + (size_t)i * Nn;
    float acc = 0.f;
    for (int t = tid; t < Nn; t += 256) acc = fmaf(row[t], g_fv[t], acc);
    acc = blockReduceSumF(acc, sh);
    if (tid == 0) g_z[i] = g_deg[i] * g_fv[i] - acc;
}

// ---------------- value = fv.z / fv.fv; normalize + sign + write --------------
__global__ void k_final(float* __restrict__ out) {
    __shared__ double sh[32];
    __shared__ float sabs[32];
    __shared__ int sidx[32];
    __shared__ double ssign;
    int tid = threadIdx.x;
    double a = (double)g_fv[tid], b = (double)g_fv[tid + 1024];
    double num = blockReduceSumD(a * (double)g_z[tid] + b * (double)g_z[tid + 1024], sh);
    double den = blockReduceSumD(a * a + b * b, sh);
    float bav; int bix;
    float fa = (float)fabs(a), fb = (float)fabs(b);
    if (fa >= fb) { bav = fa; bix = tid; }
    else          { bav = fb; bix = tid + 1024; }
#pragma unroll
    for (int o = 16; o; o >>= 1) {
        float ov = __shfl_down_sync(0xffffffffu, bav, o);
        int   oi = __shfl_down_sync(0xffffffffu, bix, o);
        if (ov > bav || (ov == bav && oi < bix)) { bav = ov; bix = oi; }
    }
    int lane = tid & 31, wid = tid >> 5;
    if (lane == 0) { sabs[wid] = bav; sidx[wid] = bix; }
    __syncthreads();
    if (tid == 0) {
        float bv = sabs[0]; int bi = sidx[0];
        for (int i = 1; i < 32; i++)
            if (sabs[i] > bv || (sabs[i] == bv && sidx[i] < bi)) { bv = sabs[i]; bi = sidx[i]; }
        ssign = (g_fv[bi] >= 0.f ? 1.0 : -1.0) * SIGN_CONV;
        out[(size_t)Nn * Nn] = (float)(num / fmax(den, 1e-300));
    }
    __syncthreads();
    double sc = ssign / sqrt(fmax(den, 1e-300));
    size_t base = (size_t)Nn * Nn + 1;
    out[base + tid]        = (float)(a * sc);
    out[base + tid + 1024] = (float)(b * sc);
}

// ---------------- launcher ----------------------------------------------------
extern "C" void kernel_launch(void* const* d_in, const int* in_sizes, int n_in,
                              void* d_out, int out_size) {
    const float* x = (const float*)d_in[0];
    const float* w = (const float*)d_in[1];
    const float* b = (const float*)d_in[2];
    float* out = (float*)d_out;
    float* G = out;   // grouping matrix lives at the front of d_out

    k_q<<<Nn, 128>>>(x, w);
    k_gemm<<<dim3(Nn / 128, Nn / 128), 256>>>(x, w, b, G);
    k_lanczos<<<NB, NT>>>(G);
    k_tridiag<<<1, 32>>>();
    k_assemble<<<Nn / 256, 256>>>();
    k_rq<<<Nn, 256>>>(G);
    k_final<<<1, 1024>>>(out);
}